// round 1
// baseline (speedup 1.0000x reference)
#include <cuda_runtime.h>
#include <cstdint>
#include <cstddef>

// ---------------- problem constants ----------------
#define BATCH 4
#define CHF   1024            // flat channels = C*4
#define NSP   4096            // H*W = 64*64
#define SCALE_ATTN 0.17677669529663687f   // 32^-0.5

// ---------------- scratch (device globals; no allocation allowed) ----------------
__device__ float g_wqkvT [1024u*3072u];          // [K=1024][M=3072]
__device__ float g_wprojT[1024u*1024u];
__device__ float g_wf1T  [1024u*2048u];
__device__ float g_wf2T  [2048u*1024u];
__device__ float g_wpe   [1024u*16u*9u];         // [oc_flat][ci_flat(16)][9]
__device__ float g_qkv   [(size_t)BATCH*3072*NSP];
__device__ float g_attno [(size_t)BATCH*CHF*NSP];
__device__ float g_o2    [(size_t)BATCH*CHF*NSP];
__device__ float g_tmp   [(size_t)BATCH*2048*NSP];
__device__ float g_x1    [(size_t)BATCH*CHF*NSP];
__device__ float g_fb    [(size_t)BATCH*2048*NSP];
__device__ float g_scale [2048];
__device__ float g_shift [2048];

// Hamilton product table: row = out component qo, col = in component qi
__constant__ int   c_comp[16] = {0,1,2,3, 1,0,3,2, 2,3,0,1, 3,2,1,0};
__constant__ float c_sign[16] = {1.f,-1.f,-1.f,-1.f,
                                 1.f, 1.f, 1.f,-1.f,
                                 1.f,-1.f, 1.f, 1.f,
                                 1.f, 1.f,-1.f, 1.f};

// ---------------- weight expansion: quaternion 1x1 conv -> real matrix [K][M] ----------------
__global__ void expand_w_kernel(const float* __restrict__ w, float* __restrict__ wT,
                                int O, int Ci) {
    int M = 4 * O, K = 4 * Ci;
    int idx = blockIdx.x * 256 + threadIdx.x;
    if (idx >= M * K) return;
    int k = idx / M, m = idx % M;
    int o = m >> 2, qo = m & 3, c = k >> 2, qi = k & 3;
    int t = qo * 4 + qi;
    wT[idx] = c_sign[t] * w[(size_t)c_comp[t] * O * Ci + (size_t)o * Ci + c];
}

// expand pe weights: out[ocf][cif][9], w_pe: [4][256][4][3][3]
__global__ void expand_pe_kernel(const float* __restrict__ w, float* __restrict__ out) {
    int idx = blockIdx.x * 256 + threadIdx.x;
    if (idx >= 1024 * 16 * 9) return;
    int kidx = idx % 9; int r = idx / 9;
    int cif = r % 16;   int ocf = r / 16;
    int o = ocf >> 2, qo = ocf & 3, ci = cif >> 2, qi = cif & 3;
    int t = qo * 4 + qi;
    out[idx] = c_sign[t] * w[(size_t)c_comp[t] * (256*4*9) + o * (4*9) + ci * 9 + kidx];
}

// ---------------- tiled SGEMM: Y[b][M][N] = AT[K][M]^T @ X[b][K][N] ----------------
#define BM 128
#define BN 128
#define BK 16

__global__ __launch_bounds__(256, 2)
void gemm_kernel(const float* __restrict__ AT, const float* __restrict__ X,
                 float* __restrict__ Y, int M, int K) {
    __shared__ float As[2][BK][BM];
    __shared__ float Bs[2][BK][BN];

    int b = blockIdx.z;
    const float* Xb = X + (size_t)b * K * NSP;
    float* Yb = Y + (size_t)b * M * NSP;
    int m0 = blockIdx.y * BM, n0 = blockIdx.x * BN;
    int t = threadIdx.x;
    int row = t >> 5;          // 0..7
    int c4  = t & 31;          // 0..31

    const float* ap0 = AT + (size_t)row * M + m0 + c4 * 4;
    const float* bp0 = Xb + (size_t)row * NSP + n0 + c4 * 4;

    float4 a0 = *(const float4*)(ap0);
    float4 a1 = *(const float4*)(ap0 + 8 * (size_t)M);
    float4 b0 = *(const float4*)(bp0);
    float4 b1 = *(const float4*)(bp0 + 8 * (size_t)NSP);

    *(float4*)&As[0][row    ][c4 * 4] = a0;
    *(float4*)&As[0][row + 8][c4 * 4] = a1;
    *(float4*)&Bs[0][row    ][c4 * 4] = b0;
    *(float4*)&Bs[0][row + 8][c4 * 4] = b1;
    __syncthreads();

    int tx = t & 15, ty = t >> 4;
    float acc[8][8];
    #pragma unroll
    for (int i = 0; i < 8; i++)
        #pragma unroll
        for (int j = 0; j < 8; j++) acc[i][j] = 0.f;

    int T = K / BK;
    int buf = 0;
    for (int kt = 0; kt < T; kt++) {
        if (kt + 1 < T) {
            const float* ap = AT + (size_t)((kt + 1) * BK + row) * M + m0 + c4 * 4;
            const float* bp = Xb + (size_t)((kt + 1) * BK + row) * NSP + n0 + c4 * 4;
            a0 = *(const float4*)(ap);
            a1 = *(const float4*)(ap + 8 * (size_t)M);
            b0 = *(const float4*)(bp);
            b1 = *(const float4*)(bp + 8 * (size_t)NSP);
        }
        #pragma unroll
        for (int kk = 0; kk < BK; kk++) {
            float4 av0 = *(const float4*)&As[buf][kk][ty * 4];
            float4 av1 = *(const float4*)&As[buf][kk][ty * 4 + 64];
            float4 bv0 = *(const float4*)&Bs[buf][kk][tx * 4];
            float4 bv1 = *(const float4*)&Bs[buf][kk][tx * 4 + 64];
            float am[8] = {av0.x, av0.y, av0.z, av0.w, av1.x, av1.y, av1.z, av1.w};
            float bn_[8] = {bv0.x, bv0.y, bv0.z, bv0.w, bv1.x, bv1.y, bv1.z, bv1.w};
            #pragma unroll
            for (int i = 0; i < 8; i++)
                #pragma unroll
                for (int j = 0; j < 8; j++) acc[i][j] += am[i] * bn_[j];
        }
        if (kt + 1 < T) {
            buf ^= 1;
            *(float4*)&As[buf][row    ][c4 * 4] = a0;
            *(float4*)&As[buf][row + 8][c4 * 4] = a1;
            *(float4*)&Bs[buf][row    ][c4 * 4] = b0;
            *(float4*)&Bs[buf][row + 8][c4 * 4] = b1;
            __syncthreads();
        }
    }

    #pragma unroll
    for (int i = 0; i < 8; i++) {
        int m = m0 + ((i < 4) ? (ty * 4 + i) : (64 + ty * 4 + i - 4));
        float* yp = Yb + (size_t)m * NSP + n0;
        *(float4*)(yp + tx * 4)      = make_float4(acc[i][0], acc[i][1], acc[i][2], acc[i][3]);
        *(float4*)(yp + tx * 4 + 64) = make_float4(acc[i][4], acc[i][5], acc[i][6], acc[i][7]);
    }
}

// ---------------- channel attention: per (b,h,q) 32x32 softmax attention over N ----------------
__global__ __launch_bounds__(256)
void attn_kernel(const float* __restrict__ qkv, float* __restrict__ o) {
    int bid = blockIdx.x;                // 0..127
    int b = bid >> 5, h = (bid >> 2) & 7, q = bid & 3;
    const float* base = qkv + (size_t)b * 3072 * NSP;
    const float* Qp = base + ((size_t)(h * 96 + 0)  * 4 + q) * NSP;
    const float* Kp = base + ((size_t)(h * 96 + 32) * 4 + q) * NSP;
    const float* Vp = base + ((size_t)(h * 96 + 64) * 4 + q) * NSP;
    const size_t RS = (size_t)4 * NSP;   // row stride between channel rows

    __shared__ float Qs[32][132];
    __shared__ float Ks[32][132];
    __shared__ float Sm[32][32];
    float* sred = &Qs[0][0];             // alias (4*32*32=4096 <= 32*132)

    int t = threadIdx.x;
    int kg = t >> 6;                     // k-split group 0..3
    int lt = t & 63;
    int c0 = lt >> 3;                    // 0..7   (c = c0 + 8i)
    int d0 = lt & 7;                     // 0..7   (d = d0 + 8j)
    int kb = kg * 32;

    float s[4][4];
    #pragma unroll
    for (int i = 0; i < 4; i++)
        #pragma unroll
        for (int j = 0; j < 4; j++) s[i][j] = 0.f;

    for (int n0 = 0; n0 < NSP; n0 += 128) {
        #pragma unroll
        for (int i = 0; i < 4; i++) {
            int fl = t + i * 256;        // 0..1023
            int r = fl >> 5, cc = fl & 31;
            *(float4*)&Qs[r][cc * 4] = *(const float4*)&Qp[(size_t)r * RS + n0 + cc * 4];
            *(float4*)&Ks[r][cc * 4] = *(const float4*)&Kp[(size_t)r * RS + n0 + cc * 4];
        }
        __syncthreads();
        for (int kk = 0; kk < 32; kk++) {
            float qv[4], kv[4];
            #pragma unroll
            for (int i = 0; i < 4; i++) qv[i] = Qs[c0 + 8 * i][kb + kk];
            #pragma unroll
            for (int j = 0; j < 4; j++) kv[j] = Ks[d0 + 8 * j][kb + kk];
            #pragma unroll
            for (int i = 0; i < 4; i++)
                #pragma unroll
                for (int j = 0; j < 4; j++) s[i][j] += qv[i] * kv[j];
        }
        __syncthreads();
    }

    #pragma unroll
    for (int i = 0; i < 4; i++)
        #pragma unroll
        for (int j = 0; j < 4; j++)
            sred[((size_t)kg * 32 + (c0 + 8 * i)) * 32 + (d0 + 8 * j)] = s[i][j];
    __syncthreads();

    if (t < 32) {
        int c = t;
        float rowv[32];
        float mx = -1e30f;
        #pragma unroll
        for (int d = 0; d < 32; d++) {
            float v = (sred[(0*32 + c)*32 + d] + sred[(1*32 + c)*32 + d] +
                       sred[(2*32 + c)*32 + d] + sred[(3*32 + c)*32 + d]) * SCALE_ATTN;
            rowv[d] = v; mx = fmaxf(mx, v);
        }
        float sum = 0.f;
        #pragma unroll
        for (int d = 0; d < 32; d++) { float e = expf(rowv[d] - mx); rowv[d] = e; sum += e; }
        float inv = 1.f / sum;
        #pragma unroll
        for (int d = 0; d < 32; d++) Sm[c][d] = rowv[d] * inv;
    }
    __syncthreads();

    float* ob = o + (size_t)b * CHF * NSP;
    for (int n = t; n < NSP; n += 256) {
        float v[32];
        #pragma unroll
        for (int d = 0; d < 32; d++) v[d] = Vp[(size_t)d * RS + n];
        #pragma unroll 4
        for (int c = 0; c < 32; c++) {
            float acc = 0.f;
            #pragma unroll
            for (int d = 0; d < 32; d++) acc += Sm[c][d] * v[d];
            ob[((size_t)((h * 32 + c) * 4 + q)) * NSP + n] = acc;
        }
    }
}

// ---------------- grouped 3x3 quaternion conv + residual: o2 = in + conv(in) ----------------
// grid: (4 ytiles, 64 groups, 4 batch), 256 threads = 16 oc x 16 y
__global__ __launch_bounds__(256)
void peconv_kernel(const float* __restrict__ in, const float* __restrict__ wpe,
                   float* __restrict__ out) {
    extern __shared__ float smem[];
    float* ins = smem;                    // [16][18][66] = 19008
    float* wts = smem + 19008;            // [16][16][9]  = 2304

    int ytile = blockIdx.x, g = blockIdx.y, b = blockIdx.z;
    int t = threadIdx.x;

    // load inputs (zero-padded borders)
    const float* inb = in + ((size_t)b * CHF + g * 16) * NSP;
    for (int idx = t; idx < 16 * 18 * 66; idx += 256) {
        int xx = idx % 66; int r = idx / 66;
        int yy = r % 18;   int ci = r / 18;
        int gy = ytile * 16 + yy - 1;
        int gx = xx - 1;
        float v = 0.f;
        if (gy >= 0 && gy < 64 && gx >= 0 && gx < 64)
            v = inb[(size_t)ci * NSP + gy * 64 + gx];
        ins[idx] = v;
    }
    for (int idx = t; idx < 16 * 16 * 9; idx += 256) {
        int kidx = idx % 9; int r = idx / 9;
        int ci = r % 16;    int oc = r / 16;
        wts[idx] = wpe[((size_t)(g * 16 + oc)) * (16 * 9) + ci * 9 + kidx];
    }
    __syncthreads();

    int oc = t >> 4, ly = t & 15;
    int gy = ytile * 16 + ly;
    const float* wrow = wts + oc * (16 * 9);
    float* outp = out + ((size_t)b * CHF + g * 16 + oc) * NSP + (size_t)gy * 64;

    for (int x0 = 0; x0 < 64; x0 += 16) {
        float acc[16];
        #pragma unroll
        for (int xi = 0; xi < 16; xi++)
            acc[xi] = ins[(oc * 18 + ly + 1) * 66 + x0 + xi + 1];   // residual
        for (int ci = 0; ci < 16; ci++) {
            #pragma unroll
            for (int kh = 0; kh < 3; kh++) {
                const float* ir = &ins[(ci * 18 + ly + kh) * 66 + x0];
                float w0 = wrow[ci * 9 + kh * 3 + 0];
                float w1 = wrow[ci * 9 + kh * 3 + 1];
                float w2 = wrow[ci * 9 + kh * 3 + 2];
                #pragma unroll
                for (int xi = 0; xi < 16; xi++)
                    acc[xi] += w0 * ir[xi] + w1 * ir[xi + 1] + w2 * ir[xi + 2];
            }
        }
        #pragma unroll
        for (int xi = 0; xi < 16; xi++) outp[x0 + xi] = acc[xi];
    }
}

// ---------------- BN stats: per flat channel over (B, N) ----------------
__global__ __launch_bounds__(256)
void stats_kernel(const float* __restrict__ Y, const float* __restrict__ gamma,
                  const float* __restrict__ beta, float* __restrict__ scale,
                  float* __restrict__ shift, int Mch) {
    int ch = blockIdx.x;
    int t = threadIdx.x;
    float s = 0.f, ss = 0.f;
    for (int b = 0; b < 4; b++) {
        const float* p = Y + ((size_t)b * Mch + ch) * NSP;
        for (int n = t; n < NSP; n += 256) { float v = p[n]; s += v; ss += v * v; }
    }
    __shared__ float rs[256], rq[256];
    rs[t] = s; rq[t] = ss;
    __syncthreads();
    for (int off = 128; off > 0; off >>= 1) {
        if (t < off) { rs[t] += rs[t + off]; rq[t] += rq[t + off]; }
        __syncthreads();
    }
    if (t == 0) {
        float cnt = 4.f * NSP;
        float mean = rs[0] / cnt;
        float var = rq[0] / cnt - mean * mean;
        float sc = gamma[ch] * rsqrtf(var + 1e-5f);
        scale[ch] = sc;
        shift[ch] = beta[ch] - mean * sc;
    }
}

// ---------------- elementwise kernels ----------------
// out = X + (Y*scale + shift)
__global__ void ew_bn_res_kernel(const float* __restrict__ X, const float* __restrict__ Yg,
                                 const float* __restrict__ sc, const float* __restrict__ sh,
                                 float* __restrict__ out, int Mch) {
    size_t i4 = (size_t)blockIdx.x * 256 + threadIdx.x;
    size_t total4 = (size_t)4 * Mch * NSP / 4;
    if (i4 >= total4) return;
    size_t i = i4 * 4;
    int ch = (int)((i / NSP) % Mch);
    float4 y = *(const float4*)(Yg + i);
    float4 x = *(const float4*)(X + i);
    float s = sc[ch], h = sh[ch];
    float4 r;
    r.x = x.x + y.x * s + h; r.y = x.y + y.y * s + h;
    r.z = x.z + y.z * s + h; r.w = x.w + y.w * s + h;
    *(float4*)(out + i) = r;
}

// out = relu(Y*scale + shift)
__global__ void ew_bn_relu_kernel(const float* __restrict__ Yg,
                                  const float* __restrict__ sc, const float* __restrict__ sh,
                                  float* __restrict__ out, int Mch) {
    size_t i4 = (size_t)blockIdx.x * 256 + threadIdx.x;
    size_t total4 = (size_t)4 * Mch * NSP / 4;
    if (i4 >= total4) return;
    size_t i = i4 * 4;
    int ch = (int)((i / NSP) % Mch);
    float4 y = *(const float4*)(Yg + i);
    float s = sc[ch], h = sh[ch];
    float4 r;
    r.x = fmaxf(y.x * s + h, 0.f); r.y = fmaxf(y.y * s + h, 0.f);
    r.z = fmaxf(y.z * s + h, 0.f); r.w = fmaxf(y.w * s + h, 0.f);
    *(float4*)(out + i) = r;
}

// ---------------- host launcher ----------------
extern "C" void kernel_launch(void* const* d_in, const int* in_sizes, int n_in,
                              void* d_out, int out_size) {
    const float* x      = (const float*)d_in[0];
    const float* w_qkv  = (const float*)d_in[1];
    const float* w_proj = (const float*)d_in[2];
    const float* w_pe   = (const float*)d_in[3];
    const float* gn     = (const float*)d_in[4];
    const float* bn     = (const float*)d_in[5];
    const float* w_f1   = (const float*)d_in[6];
    const float* gf1    = (const float*)d_in[7];
    const float* bf1    = (const float*)d_in[8];
    const float* w_f2   = (const float*)d_in[9];
    const float* gf2    = (const float*)d_in[10];
    const float* bf2    = (const float*)d_in[11];
    float* out = (float*)d_out;

    void *p;
    float *wqkvT, *wprojT, *wf1T, *wf2T, *wpe, *qkv, *attno, *o2, *tmp, *x1, *fb, *sc, *sh;
    cudaGetSymbolAddress(&p, g_wqkvT);  wqkvT  = (float*)p;
    cudaGetSymbolAddress(&p, g_wprojT); wprojT = (float*)p;
    cudaGetSymbolAddress(&p, g_wf1T);   wf1T   = (float*)p;
    cudaGetSymbolAddress(&p, g_wf2T);   wf2T   = (float*)p;
    cudaGetSymbolAddress(&p, g_wpe);    wpe    = (float*)p;
    cudaGetSymbolAddress(&p, g_qkv);    qkv    = (float*)p;
    cudaGetSymbolAddress(&p, g_attno);  attno  = (float*)p;
    cudaGetSymbolAddress(&p, g_o2);     o2     = (float*)p;
    cudaGetSymbolAddress(&p, g_tmp);    tmp    = (float*)p;
    cudaGetSymbolAddress(&p, g_x1);     x1     = (float*)p;
    cudaGetSymbolAddress(&p, g_fb);     fb     = (float*)p;
    cudaGetSymbolAddress(&p, g_scale);  sc     = (float*)p;
    cudaGetSymbolAddress(&p, g_shift);  sh     = (float*)p;

    // 1. weight expansions
    expand_w_kernel<<<(3072 * 1024 + 255) / 256, 256>>>(w_qkv,  wqkvT,  768, 256);
    expand_w_kernel<<<(1024 * 1024 + 255) / 256, 256>>>(w_proj, wprojT, 256, 256);
    expand_w_kernel<<<(2048 * 1024 + 255) / 256, 256>>>(w_f1,   wf1T,   512, 256);
    expand_w_kernel<<<(1024 * 2048 + 255) / 256, 256>>>(w_f2,   wf2T,   256, 512);
    expand_pe_kernel<<<(1024 * 16 * 9 + 255) / 256, 256>>>(w_pe, wpe);

    // 2. qkv GEMM: [3072x1024] @ x
    gemm_kernel<<<dim3(NSP / BN, 3072 / BM, BATCH), 256>>>(wqkvT, x, qkv, 3072, 1024);

    // 3. channel attention
    attn_kernel<<<128, 256>>>(qkv, attno);

    // 4. positional 3x3 grouped quaternion conv + residual
    static const int PE_SMEM = (19008 + 2304) * 4;
    cudaFuncSetAttribute(peconv_kernel, cudaFuncAttributeMaxDynamicSharedMemorySize, PE_SMEM);
    peconv_kernel<<<dim3(4, 64, BATCH), 256, PE_SMEM>>>(attno, wpe, o2);

    // 5. proj GEMM + BN + residual -> x1
    gemm_kernel<<<dim3(NSP / BN, 1024 / BM, BATCH), 256>>>(wprojT, o2, tmp, 1024, 1024);
    stats_kernel<<<1024, 256>>>(tmp, gn, bn, sc, sh, 1024);
    ew_bn_res_kernel<<<(int)((size_t)4 * 1024 * NSP / 4 / 256), 256>>>(x, tmp, sc, sh, x1, 1024);

    // 6. f1 GEMM + BN + relu -> fb
    gemm_kernel<<<dim3(NSP / BN, 2048 / BM, BATCH), 256>>>(wf1T, x1, tmp, 2048, 1024);
    stats_kernel<<<2048, 256>>>(tmp, gf1, bf1, sc, sh, 2048);
    ew_bn_relu_kernel<<<(int)((size_t)4 * 2048 * NSP / 4 / 256), 256>>>(tmp, sc, sh, fb, 2048);

    // 7. f2 GEMM + BN + residual -> out
    gemm_kernel<<<dim3(NSP / BN, 1024 / BM, BATCH), 256>>>(wf2T, fb, tmp, 1024, 2048);
    stats_kernel<<<1024, 256>>>(tmp, gf2, bf2, sc, sh, 1024);
    ew_bn_res_kernel<<<(int)((size_t)4 * 1024 * NSP / 4 / 256), 256>>>(x1, tmp, sc, sh, out, 1024);

    (void)in_sizes; (void)n_in; (void)out_size;
}

// round 4
// speedup vs baseline: 1.7506x; 1.7506x over previous
#include <cuda_runtime.h>
#include <cuda_bf16.h>
#include <cstdint>
#include <cstddef>

// ---------------- problem constants ----------------
#define BATCH 4
#define CHF   1024            // flat channels = C*4
#define NSP   4096            // H*W = 64*64
#define SCALE_ATTN 0.17677669529663687f

// ---------------- scratch ----------------
// packed bf16 k-pair weight planes: [K/2][M] uint32 words (low16 = even k)
__device__ __align__(16) uint32_t g_wqkv_h [512u*3072u];
__device__ __align__(16) uint32_t g_wqkv_l [512u*3072u];
__device__ __align__(16) uint32_t g_wproj_h[512u*1024u];
__device__ __align__(16) uint32_t g_wproj_l[512u*1024u];
__device__ __align__(16) uint32_t g_wf1_h  [512u*2048u];
__device__ __align__(16) uint32_t g_wf1_l  [512u*2048u];
__device__ __align__(16) uint32_t g_wf2_h  [1024u*1024u];
__device__ __align__(16) uint32_t g_wf2_l  [1024u*1024u];
__device__ __align__(16) float g_wpe   [1024u*16u*9u];
__device__ __align__(16) float g_qkv   [(size_t)BATCH*3072*NSP];
__device__ __align__(16) float g_attno [(size_t)BATCH*CHF*NSP];
__device__ __align__(16) float g_o2    [(size_t)BATCH*CHF*NSP];
__device__ __align__(16) float g_tmp   [(size_t)BATCH*2048*NSP];
__device__ __align__(16) float g_x1    [(size_t)BATCH*CHF*NSP];
__device__ __align__(16) float g_fb    [(size_t)BATCH*2048*NSP];
__device__ float g_scale [2048];
__device__ float g_shift [2048];

__constant__ int   c_comp[16] = {0,1,2,3, 1,0,3,2, 2,3,0,1, 3,2,1,0};
__constant__ float c_sign[16] = {1.f,-1.f,-1.f,-1.f,
                                 1.f, 1.f, 1.f,-1.f,
                                 1.f,-1.f, 1.f, 1.f,
                                 1.f, 1.f,-1.f, 1.f};

// ---------------- helpers ----------------
__device__ __forceinline__ void mma16(float c[4], const uint32_t a[4], const uint32_t b[2]) {
    asm volatile("mma.sync.aligned.m16n8k16.row.col.f32.bf16.bf16.f32 "
        "{%0,%1,%2,%3}, {%4,%5,%6,%7}, {%8,%9}, {%0,%1,%2,%3};"
        : "+f"(c[0]), "+f"(c[1]), "+f"(c[2]), "+f"(c[3])
        : "r"(a[0]), "r"(a[1]), "r"(a[2]), "r"(a[3]), "r"(b[0]), "r"(b[1]));
}
// pack two fp32 into bf16x2 (v0 in low 16), and compute residuals
__device__ __forceinline__ void split2(float v0, float v1, uint32_t& wh, uint32_t& wl) {
    __nv_bfloat162 h = __floats2bfloat162_rn(v0, v1);
    wh = *(uint32_t*)&h;
    float r0 = v0 - __uint_as_float(wh << 16);
    float r1 = v1 - __uint_as_float(wh & 0xFFFF0000u);
    __nv_bfloat162 l = __floats2bfloat162_rn(r0, r1);
    wl = *(uint32_t*)&l;
}

// ---------------- weight expansion: quaternion 1x1 -> packed bf16 planes [K/2][M] ----------------
__global__ void expand_w_pk(const float* __restrict__ w, uint32_t* __restrict__ hi,
                            uint32_t* __restrict__ lo, int O, int Ci) {
    int M = 4 * O, KP2 = 2 * Ci;
    int idx = blockIdx.x * 256 + threadIdx.x;
    if (idx >= KP2 * M) return;
    int kp = idx / M, m = idx % M;
    int o = m >> 2, qo = m & 3;
    float v[2];
    #pragma unroll
    for (int j = 0; j < 2; j++) {
        int k = 2 * kp + j;
        int cc = k >> 2, qi = k & 3;
        int tt = qo * 4 + qi;
        v[j] = c_sign[tt] * w[(size_t)c_comp[tt] * O * Ci + (size_t)o * Ci + cc];
    }
    uint32_t wh, wl;
    split2(v[0], v[1], wh, wl);
    hi[idx] = wh; lo[idx] = wl;
}

__global__ void expand_pe_kernel(const float* __restrict__ w, float* __restrict__ out) {
    int idx = blockIdx.x * 256 + threadIdx.x;
    if (idx >= 1024 * 16 * 9) return;
    int kidx = idx % 9; int r = idx / 9;
    int cif = r % 16;   int ocf = r / 16;
    int o = ocf >> 2, qo = ocf & 3, ci = cif >> 2, qi = cif & 3;
    int t = qo * 4 + qi;
    out[idx] = c_sign[t] * w[(size_t)c_comp[t] * (256*4*9) + o * (4*9) + ci * 9 + kidx];
}

// ---------------- bf16x3 mma GEMM: Y[b][M][N] = W[M][K] @ X[b][K][N] ----------------
// CTA tile 128x128, BK=32 (16 packed kp rows/chunk), 256 threads = 8 warps (2m x 4n),
// warp tile 64x32. Smem: 2 bufs x {Ahi, Alo, Bhi, Blo} planes of [16][136] words.
#define KPC   16
#define PSTR  136
#define PLANEW (KPC * PSTR)
#define GEMM_SMEM_BYTES (2 * 4 * PLANEW * 4)

__global__ __launch_bounds__(256)
void mma_gemm(const uint32_t* __restrict__ Ah_g, const uint32_t* __restrict__ Al_g,
              const float* __restrict__ X, float* __restrict__ Y, int M, int K) {
    extern __shared__ uint32_t sm[];
    int t = threadIdx.x;
    int wid = t >> 5, lane = t & 31;
    int gid = lane >> 2, tig = lane & 3;
    int wm = (wid >> 2) * 64, wn = (wid & 3) * 32;
    int m0 = blockIdx.y * 128, n0 = blockIdx.x * 128, b = blockIdx.z;
    const float* Xb = X + (size_t)b * K * NSP;
    float* Yb = Y + (size_t)b * M * NSP;

    int kp = t >> 4, s8 = (t & 15) * 8;   // staging: plane row kp, word cols s8..s8+7

    float c[4][4][4];
    #pragma unroll
    for (int mi = 0; mi < 4; mi++)
        #pragma unroll
        for (int nj = 0; nj < 4; nj++)
            #pragma unroll
            for (int q = 0; q < 4; q++) c[mi][nj][q] = 0.f;

    uint4 a_h[2], a_l[2];
    float4 bx[4];   // bx[0..1]: k-even row, bx[2..3]: k-odd row

    auto ldg_chunk = [&](int kc) {
        const uint4* pah = (const uint4*)(Ah_g + (size_t)(kc * KPC + kp) * M + m0 + s8);
        a_h[0] = pah[0]; a_h[1] = pah[1];
        const uint4* pal = (const uint4*)(Al_g + (size_t)(kc * KPC + kp) * M + m0 + s8);
        a_l[0] = pal[0]; a_l[1] = pal[1];
        const float4* pb0 = (const float4*)(Xb + (size_t)(kc * 32 + 2 * kp) * NSP + n0 + s8);
        bx[0] = pb0[0]; bx[1] = pb0[1];
        const float4* pb1 = (const float4*)(Xb + (size_t)(kc * 32 + 2 * kp + 1) * NSP + n0 + s8);
        bx[2] = pb1[0]; bx[3] = pb1[1];
    };
    auto sts_chunk = [&](int dbuf) {
        uint32_t* S = sm + dbuf * 4 * PLANEW;
        *(uint4*)(S + kp * PSTR + s8)                  = a_h[0];
        *(uint4*)(S + kp * PSTR + s8 + 4)              = a_h[1];
        *(uint4*)(S + PLANEW + kp * PSTR + s8)         = a_l[0];
        *(uint4*)(S + PLANEW + kp * PSTR + s8 + 4)     = a_l[1];
        uint32_t wh[8], wl[8];
        const float* e0 = (const float*)&bx[0];
        const float* e1 = (const float*)&bx[2];
        #pragma unroll
        for (int j = 0; j < 8; j++) split2(e0[j], e1[j], wh[j], wl[j]);
        *(uint4*)(S + 2 * PLANEW + kp * PSTR + s8)     = make_uint4(wh[0], wh[1], wh[2], wh[3]);
        *(uint4*)(S + 2 * PLANEW + kp * PSTR + s8 + 4) = make_uint4(wh[4], wh[5], wh[6], wh[7]);
        *(uint4*)(S + 3 * PLANEW + kp * PSTR + s8)     = make_uint4(wl[0], wl[1], wl[2], wl[3]);
        *(uint4*)(S + 3 * PLANEW + kp * PSTR + s8 + 4) = make_uint4(wl[4], wl[5], wl[6], wl[7]);
    };

    ldg_chunk(0);
    sts_chunk(0);

    int T = K / 32;
    int buf = 0;
    for (int kc = 0; kc < T; kc++) {
        __syncthreads();
        bool more = (kc + 1 < T);
        if (more) ldg_chunk(kc + 1);

        const uint32_t* Ah = sm + buf * 4 * PLANEW;
        const uint32_t* Al = Ah + PLANEW;
        const uint32_t* Bh = Ah + 2 * PLANEW;
        const uint32_t* Bl = Ah + 3 * PLANEW;

        #pragma unroll
        for (int st = 0; st < 2; st++) {
            int r0 = (st * 8 + tig) * PSTR, r1 = r0 + 4 * PSTR;
            uint32_t ah[4][4], bh[4][2];
            #pragma unroll
            for (int mi = 0; mi < 4; mi++) {
                int mo = wm + 16 * mi + gid;
                ah[mi][0] = Ah[r0 + mo]; ah[mi][1] = Ah[r0 + mo + 8];
                ah[mi][2] = Ah[r1 + mo]; ah[mi][3] = Ah[r1 + mo + 8];
            }
            #pragma unroll
            for (int nj = 0; nj < 4; nj++) {
                int no = wn + 8 * nj + gid;
                bh[nj][0] = Bh[r0 + no]; bh[nj][1] = Bh[r1 + no];
            }
            #pragma unroll
            for (int mi = 0; mi < 4; mi++)
                #pragma unroll
                for (int nj = 0; nj < 4; nj++) mma16(c[mi][nj], ah[mi], bh[nj]);
            {
                uint32_t bl[4][2];
                #pragma unroll
                for (int nj = 0; nj < 4; nj++) {
                    int no = wn + 8 * nj + gid;
                    bl[nj][0] = Bl[r0 + no]; bl[nj][1] = Bl[r1 + no];
                }
                #pragma unroll
                for (int mi = 0; mi < 4; mi++)
                    #pragma unroll
                    for (int nj = 0; nj < 4; nj++) mma16(c[mi][nj], ah[mi], bl[nj]);
            }
            {
                uint32_t al[4][4];
                #pragma unroll
                for (int mi = 0; mi < 4; mi++) {
                    int mo = wm + 16 * mi + gid;
                    al[mi][0] = Al[r0 + mo]; al[mi][1] = Al[r0 + mo + 8];
                    al[mi][2] = Al[r1 + mo]; al[mi][3] = Al[r1 + mo + 8];
                }
                #pragma unroll
                for (int mi = 0; mi < 4; mi++)
                    #pragma unroll
                    for (int nj = 0; nj < 4; nj++) mma16(c[mi][nj], al[mi], bh[nj]);
            }
            if (st == 0 && more) sts_chunk(buf ^ 1);
        }
        buf ^= 1;
    }

    // epilogue: c frag rows gid/gid+8, cols 2tig/2tig+1
    #pragma unroll
    for (int mi = 0; mi < 4; mi++) {
        int m = m0 + wm + 16 * mi + gid;
        float* y0 = Yb + (size_t)m * NSP + n0 + wn + 2 * tig;
        float* y1 = y0 + (size_t)8 * NSP;
        #pragma unroll
        for (int nj = 0; nj < 4; nj++) {
            *(float2*)(y0 + nj * 8) = make_float2(c[mi][nj][0], c[mi][nj][1]);
            *(float2*)(y1 + nj * 8) = make_float2(c[mi][nj][2], c[mi][nj][3]);
        }
    }
}

// ---------------- channel attention ----------------
__global__ __launch_bounds__(256)
void attn_kernel(const float* __restrict__ qkv, float* __restrict__ o) {
    int bid = blockIdx.x;
    int b = bid >> 5, h = (bid >> 2) & 7, q = bid & 3;
    const float* base = qkv + (size_t)b * 3072 * NSP;
    const float* Qp = base + ((size_t)(h * 96 + 0)  * 4 + q) * NSP;
    const float* Kp = base + ((size_t)(h * 96 + 32) * 4 + q) * NSP;
    const float* Vp = base + ((size_t)(h * 96 + 64) * 4 + q) * NSP;
    const size_t RS = (size_t)4 * NSP;

    __shared__ float Qs[32][132];
    __shared__ float Ks[32][132];
    __shared__ float Sm[32][32];
    float* sred = &Qs[0][0];

    int t = threadIdx.x;
    int kg = t >> 6, lt = t & 63;
    int c0 = lt >> 3, d0 = lt & 7, kb = kg * 32;

    float s[4][4];
    #pragma unroll
    for (int i = 0; i < 4; i++)
        #pragma unroll
        for (int j = 0; j < 4; j++) s[i][j] = 0.f;

    for (int n0 = 0; n0 < NSP; n0 += 128) {
        #pragma unroll
        for (int i = 0; i < 4; i++) {
            int fl = t + i * 256;
            int r = fl >> 5, cc = fl & 31;
            *(float4*)&Qs[r][cc * 4] = *(const float4*)&Qp[(size_t)r * RS + n0 + cc * 4];
            *(float4*)&Ks[r][cc * 4] = *(const float4*)&Kp[(size_t)r * RS + n0 + cc * 4];
        }
        __syncthreads();
        for (int kk = 0; kk < 32; kk++) {
            float qv[4], kv[4];
            #pragma unroll
            for (int i = 0; i < 4; i++) qv[i] = Qs[c0 + 8 * i][kb + kk];
            #pragma unroll
            for (int j = 0; j < 4; j++) kv[j] = Ks[d0 + 8 * j][kb + kk];
            #pragma unroll
            for (int i = 0; i < 4; i++)
                #pragma unroll
                for (int j = 0; j < 4; j++) s[i][j] += qv[i] * kv[j];
        }
        __syncthreads();
    }
    #pragma unroll
    for (int i = 0; i < 4; i++)
        #pragma unroll
        for (int j = 0; j < 4; j++)
            sred[((size_t)kg * 32 + (c0 + 8 * i)) * 32 + (d0 + 8 * j)] = s[i][j];
    __syncthreads();

    if (t < 32) {
        int c = t;
        float rowv[32];
        float mx = -1e30f;
        #pragma unroll
        for (int d = 0; d < 32; d++) {
            float v = (sred[(0*32 + c)*32 + d] + sred[(1*32 + c)*32 + d] +
                       sred[(2*32 + c)*32 + d] + sred[(3*32 + c)*32 + d]) * SCALE_ATTN;
            rowv[d] = v; mx = fmaxf(mx, v);
        }
        float sum = 0.f;
        #pragma unroll
        for (int d = 0; d < 32; d++) { float e = expf(rowv[d] - mx); rowv[d] = e; sum += e; }
        float inv = 1.f / sum;
        #pragma unroll
        for (int d = 0; d < 32; d++) Sm[c][d] = rowv[d] * inv;
    }
    __syncthreads();

    float* ob = o + (size_t)b * CHF * NSP;
    for (int n = t; n < NSP; n += 256) {
        float v[32];
        #pragma unroll
        for (int d = 0; d < 32; d++) v[d] = Vp[(size_t)d * RS + n];
        #pragma unroll 4
        for (int c = 0; c < 32; c++) {
            float acc = 0.f;
            #pragma unroll
            for (int d = 0; d < 32; d++) acc += Sm[c][d] * v[d];
            ob[((size_t)((h * 32 + c) * 4 + q)) * NSP + n] = acc;
        }
    }
}

// ---------------- grouped 3x3 quaternion conv + residual ----------------
__global__ __launch_bounds__(256)
void peconv_kernel(const float* __restrict__ in, const float* __restrict__ wpe,
                   float* __restrict__ out) {
    extern __shared__ float smem[];
    float* ins = smem;
    float* wts = smem + 19008;

    int ytile = blockIdx.x, g = blockIdx.y, b = blockIdx.z;
    int t = threadIdx.x;

    const float* inb = in + ((size_t)b * CHF + g * 16) * NSP;
    for (int idx = t; idx < 16 * 18 * 66; idx += 256) {
        int xx = idx % 66; int r = idx / 66;
        int yy = r % 18;   int ci = r / 18;
        int gy = ytile * 16 + yy - 1;
        int gx = xx - 1;
        float v = 0.f;
        if (gy >= 0 && gy < 64 && gx >= 0 && gx < 64)
            v = inb[(size_t)ci * NSP + gy * 64 + gx];
        ins[idx] = v;
    }
    for (int idx = t; idx < 16 * 16 * 9; idx += 256) {
        int kidx = idx % 9; int r = idx / 9;
        int ci = r % 16;    int oc = r / 16;
        wts[idx] = wpe[((size_t)(g * 16 + oc)) * (16 * 9) + ci * 9 + kidx];
    }
    __syncthreads();

    int oc = t >> 4, ly = t & 15;
    int gy = ytile * 16 + ly;
    const float* wrow = wts + oc * (16 * 9);
    float* outp = out + ((size_t)b * CHF + g * 16 + oc) * NSP + (size_t)gy * 64;

    for (int x0 = 0; x0 < 64; x0 += 16) {
        float acc[16];
        #pragma unroll
        for (int xi = 0; xi < 16; xi++)
            acc[xi] = ins[(oc * 18 + ly + 1) * 66 + x0 + xi + 1];
        for (int ci = 0; ci < 16; ci++) {
            #pragma unroll
            for (int kh = 0; kh < 3; kh++) {
                const float* ir = &ins[(ci * 18 + ly + kh) * 66 + x0];
                float w0 = wrow[ci * 9 + kh * 3 + 0];
                float w1 = wrow[ci * 9 + kh * 3 + 1];
                float w2 = wrow[ci * 9 + kh * 3 + 2];
                #pragma unroll
                for (int xi = 0; xi < 16; xi++)
                    acc[xi] += w0 * ir[xi] + w1 * ir[xi + 1] + w2 * ir[xi + 2];
            }
        }
        #pragma unroll
        for (int xi = 0; xi < 16; xi++) outp[x0 + xi] = acc[xi];
    }
}

// ---------------- BN stats ----------------
__global__ __launch_bounds__(256)
void stats_kernel(const float* __restrict__ Y, const float* __restrict__ gamma,
                  const float* __restrict__ beta, float* __restrict__ scale,
                  float* __restrict__ shift, int Mch) {
    int ch = blockIdx.x;
    int t = threadIdx.x;
    float s = 0.f, ss = 0.f;
    for (int b = 0; b < 4; b++) {
        const float* p = Y + ((size_t)b * Mch + ch) * NSP;
        for (int n = t; n < NSP; n += 256) { float v = p[n]; s += v; ss += v * v; }
    }
    __shared__ float rs[256], rq[256];
    rs[t] = s; rq[t] = ss;
    __syncthreads();
    for (int off = 128; off > 0; off >>= 1) {
        if (t < off) { rs[t] += rs[t + off]; rq[t] += rq[t + off]; }
        __syncthreads();
    }
    if (t == 0) {
        float cnt = 4.f * NSP;
        float mean = rs[0] / cnt;
        float var = rq[0] / cnt - mean * mean;
        float sc = gamma[ch] * rsqrtf(var + 1e-5f);
        scale[ch] = sc;
        shift[ch] = beta[ch] - mean * sc;
    }
}

// ---------------- elementwise ----------------
__global__ void ew_bn_res_kernel(const float* __restrict__ X, const float* __restrict__ Yg,
                                 const float* __restrict__ sc, const float* __restrict__ sh,
                                 float* __restrict__ out, int Mch) {
    size_t i4 = (size_t)blockIdx.x * 256 + threadIdx.x;
    size_t total4 = (size_t)4 * Mch * NSP / 4;
    if (i4 >= total4) return;
    size_t i = i4 * 4;
    int ch = (int)((i / NSP) % Mch);
    float4 y = *(const float4*)(Yg + i);
    float4 x = *(const float4*)(X + i);
    float s = sc[ch], h = sh[ch];
    float4 r;
    r.x = x.x + y.x * s + h; r.y = x.y + y.y * s + h;
    r.z = x.z + y.z * s + h; r.w = x.w + y.w * s + h;
    *(float4*)(out + i) = r;
}

__global__ void ew_bn_relu_kernel(const float* __restrict__ Yg,
                                  const float* __restrict__ sc, const float* __restrict__ sh,
                                  float* __restrict__ out, int Mch) {
    size_t i4 = (size_t)blockIdx.x * 256 + threadIdx.x;
    size_t total4 = (size_t)4 * Mch * NSP / 4;
    if (i4 >= total4) return;
    size_t i = i4 * 4;
    int ch = (int)((i / NSP) % Mch);
    float4 y = *(const float4*)(Yg + i);
    float s = sc[ch], h = sh[ch];
    float4 r;
    r.x = fmaxf(y.x * s + h, 0.f); r.y = fmaxf(y.y * s + h, 0.f);
    r.z = fmaxf(y.z * s + h, 0.f); r.w = fmaxf(y.w * s + h, 0.f);
    *(float4*)(out + i) = r;
}

// ---------------- host launcher ----------------
extern "C" void kernel_launch(void* const* d_in, const int* in_sizes, int n_in,
                              void* d_out, int out_size) {
    const float* x      = (const float*)d_in[0];
    const float* w_qkv  = (const float*)d_in[1];
    const float* w_proj = (const float*)d_in[2];
    const float* w_pe   = (const float*)d_in[3];
    const float* gn     = (const float*)d_in[4];
    const float* bn     = (const float*)d_in[5];
    const float* w_f1   = (const float*)d_in[6];
    const float* gf1    = (const float*)d_in[7];
    const float* bf1    = (const float*)d_in[8];
    const float* w_f2   = (const float*)d_in[9];
    const float* gf2    = (const float*)d_in[10];
    const float* bf2    = (const float*)d_in[11];
    float* out = (float*)d_out;

    void *p;
    uint32_t *qh, *ql, *ph, *pl, *f1h, *f1l, *f2h, *f2l;
    float *wpe, *qkv, *attno, *o2, *tmp, *x1, *fb, *sc, *sh;
    cudaGetSymbolAddress(&p, g_wqkv_h);  qh  = (uint32_t*)p;
    cudaGetSymbolAddress(&p, g_wqkv_l);  ql  = (uint32_t*)p;
    cudaGetSymbolAddress(&p, g_wproj_h); ph  = (uint32_t*)p;
    cudaGetSymbolAddress(&p, g_wproj_l); pl  = (uint32_t*)p;
    cudaGetSymbolAddress(&p, g_wf1_h);   f1h = (uint32_t*)p;
    cudaGetSymbolAddress(&p, g_wf1_l);   f1l = (uint32_t*)p;
    cudaGetSymbolAddress(&p, g_wf2_h);   f2h = (uint32_t*)p;
    cudaGetSymbolAddress(&p, g_wf2_l);   f2l = (uint32_t*)p;
    cudaGetSymbolAddress(&p, g_wpe);     wpe = (float*)p;
    cudaGetSymbolAddress(&p, g_qkv);     qkv = (float*)p;
    cudaGetSymbolAddress(&p, g_attno);   attno = (float*)p;
    cudaGetSymbolAddress(&p, g_o2);      o2  = (float*)p;
    cudaGetSymbolAddress(&p, g_tmp);     tmp = (float*)p;
    cudaGetSymbolAddress(&p, g_x1);      x1  = (float*)p;
    cudaGetSymbolAddress(&p, g_fb);      fb  = (float*)p;
    cudaGetSymbolAddress(&p, g_scale);   sc  = (float*)p;
    cudaGetSymbolAddress(&p, g_shift);   sh  = (float*)p;

    cudaFuncSetAttribute(mma_gemm, cudaFuncAttributeMaxDynamicSharedMemorySize, GEMM_SMEM_BYTES);
    static const int PE_SMEM = (19008 + 2304) * 4;
    cudaFuncSetAttribute(peconv_kernel, cudaFuncAttributeMaxDynamicSharedMemorySize, PE_SMEM);

    // 1. weight expansions -> packed bf16 hi/lo planes
    expand_w_pk<<<(512 * 3072 + 255) / 256, 256>>>(w_qkv,  qh,  ql,  768, 256);
    expand_w_pk<<<(512 * 1024 + 255) / 256, 256>>>(w_proj, ph,  pl,  256, 256);
    expand_w_pk<<<(512 * 2048 + 255) / 256, 256>>>(w_f1,   f1h, f1l, 512, 256);
    expand_w_pk<<<(1024 * 1024 + 255) / 256, 256>>>(w_f2,  f2h, f2l, 256, 512);
    expand_pe_kernel<<<(1024 * 16 * 9 + 255) / 256, 256>>>(w_pe, wpe);

    // 2. qkv GEMM
    mma_gemm<<<dim3(32, 24, BATCH), 256, GEMM_SMEM_BYTES>>>(qh, ql, x, qkv, 3072, 1024);

    // 3. channel attention
    attn_kernel<<<128, 256>>>(qkv, attno);

    // 4. positional conv + residual
    peconv_kernel<<<dim3(4, 64, BATCH), 256, PE_SMEM>>>(attno, wpe, o2);

    // 5. proj GEMM + BN + residual
    mma_gemm<<<dim3(32, 8, BATCH), 256, GEMM_SMEM_BYTES>>>(ph, pl, o2, tmp, 1024, 1024);
    stats_kernel<<<1024, 256>>>(tmp, gn, bn, sc, sh, 1024);
    ew_bn_res_kernel<<<(int)((size_t)4 * 1024 * NSP / 4 / 256), 256>>>(x, tmp, sc, sh, x1, 1024);

    // 6. f1 GEMM + BN + relu
    mma_gemm<<<dim3(32, 16, BATCH), 256, GEMM_SMEM_BYTES>>>(f1h, f1l, x1, tmp, 2048, 1024);
    stats_kernel<<<2048, 256>>>(tmp, gf1, bf1, sc, sh, 2048);
    ew_bn_relu_kernel<<<(int)((size_t)4 * 2048 * NSP / 4 / 256), 256>>>(tmp, sc, sh, fb, 2048);

    // 7. f2 GEMM + BN + residual -> out
    mma_gemm<<<dim3(32, 8, BATCH), 256, GEMM_SMEM_BYTES>>>(f2h, f2l, fb, tmp, 1024, 2048);
    stats_kernel<<<1024, 256>>>(tmp, gf2, bf2, sc, sh, 1024);
    ew_bn_res_kernel<<<(int)((size_t)4 * 1024 * NSP / 4 / 256), 256>>>(x1, tmp, sc, sh, out, 1024);

    (void)in_sizes; (void)n_in; (void)out_size;
}

// round 5
// speedup vs baseline: 2.2967x; 1.3119x over previous
#include <cuda_runtime.h>
#include <cuda_bf16.h>
#include <cstdint>
#include <cstddef>

// ---------------- problem constants ----------------
#define BATCH 4
#define CHF   1024            // flat channels = C*4
#define NSP   4096            // H*W = 64*64
#define SCALE_ATTN 0.17677669529663687f

// ---------------- scratch ----------------
// packed bf16 k-pair weight planes: [K/2][M] uint32 words (low16 = even k)
__device__ __align__(16) uint32_t g_wqkv_h [512u*3072u];
__device__ __align__(16) uint32_t g_wqkv_l [512u*3072u];
__device__ __align__(16) uint32_t g_wproj_h[512u*1024u];
__device__ __align__(16) uint32_t g_wproj_l[512u*1024u];
__device__ __align__(16) uint32_t g_wf1_h  [512u*2048u];
__device__ __align__(16) uint32_t g_wf1_l  [512u*2048u];
__device__ __align__(16) uint32_t g_wf2_h  [1024u*1024u];
__device__ __align__(16) uint32_t g_wf2_l  [1024u*1024u];
// packed bf16 activation planes: [b][K/2][NSP]
__device__ __align__(16) uint32_t g_xh  [(size_t)BATCH*512*NSP];
__device__ __align__(16) uint32_t g_xl  [(size_t)BATCH*512*NSP];
__device__ __align__(16) uint32_t g_o2h [(size_t)BATCH*512*NSP];
__device__ __align__(16) uint32_t g_o2l [(size_t)BATCH*512*NSP];
__device__ __align__(16) uint32_t g_x1h [(size_t)BATCH*512*NSP];
__device__ __align__(16) uint32_t g_x1l [(size_t)BATCH*512*NSP];
__device__ __align__(16) uint32_t g_fbh [(size_t)BATCH*1024*NSP];
__device__ __align__(16) uint32_t g_fbl [(size_t)BATCH*1024*NSP];

__device__ __align__(16) float g_wpe   [1024u*16u*9u];
__device__ __align__(16) float g_qkv   [(size_t)BATCH*3072*NSP];
__device__ __align__(16) float g_attno [(size_t)BATCH*CHF*NSP];
__device__ __align__(16) float g_o2    [(size_t)BATCH*CHF*NSP];
__device__ __align__(16) float g_tmp   [(size_t)BATCH*2048*NSP];
__device__ __align__(16) float g_x1    [(size_t)BATCH*CHF*NSP];
__device__ float g_scale [2048];
__device__ float g_shift [2048];

__constant__ int   c_comp[16] = {0,1,2,3, 1,0,3,2, 2,3,0,1, 3,2,1,0};
__constant__ float c_sign[16] = {1.f,-1.f,-1.f,-1.f,
                                 1.f, 1.f, 1.f,-1.f,
                                 1.f,-1.f, 1.f, 1.f,
                                 1.f, 1.f,-1.f, 1.f};

// ---------------- helpers ----------------
__device__ __forceinline__ uint32_t smem_u32(const void* p) {
    uint32_t a;
    asm("{ .reg .u64 t; cvta.to.shared.u64 t, %1; cvt.u32.u64 %0, t; }" : "=r"(a) : "l"(p));
    return a;
}
__device__ __forceinline__ void mma16(float c[4], const uint32_t a[4], const uint32_t b[2]) {
    asm volatile("mma.sync.aligned.m16n8k16.row.col.f32.bf16.bf16.f32 "
        "{%0,%1,%2,%3}, {%4,%5,%6,%7}, {%8,%9}, {%0,%1,%2,%3};"
        : "+f"(c[0]), "+f"(c[1]), "+f"(c[2]), "+f"(c[3])
        : "r"(a[0]), "r"(a[1]), "r"(a[2]), "r"(a[3]), "r"(b[0]), "r"(b[1]));
}
// pack two fp32 into bf16x2 (v0 in low 16), plus residual pack
__device__ __forceinline__ void split2(float v0, float v1, uint32_t& wh, uint32_t& wl) {
    __nv_bfloat162 h = __floats2bfloat162_rn(v0, v1);
    wh = *(uint32_t*)&h;
    float r0 = v0 - __uint_as_float(wh << 16);
    float r1 = v1 - __uint_as_float(wh & 0xFFFF0000u);
    __nv_bfloat162 l = __floats2bfloat162_rn(r0, r1);
    wl = *(uint32_t*)&l;
}
__device__ __forceinline__ void cp16(uint32_t sa, const void* ga) {
    asm volatile("cp.async.cg.shared.global [%0], [%1], 16;" :: "r"(sa), "l"(ga));
}
#define CP_COMMIT() asm volatile("cp.async.commit_group;" ::: "memory")
#define CP_WAIT0()  asm volatile("cp.async.wait_group 0;" ::: "memory")

// ---------------- weight expansion ----------------
__global__ void expand_w_pk(const float* __restrict__ w, uint32_t* __restrict__ hi,
                            uint32_t* __restrict__ lo, int O, int Ci) {
    int M = 4 * O, KP2 = 2 * Ci;
    int idx = blockIdx.x * 256 + threadIdx.x;
    if (idx >= KP2 * M) return;
    int kp = idx / M, m = idx % M;
    int o = m >> 2, qo = m & 3;
    float v[2];
    #pragma unroll
    for (int j = 0; j < 2; j++) {
        int k = 2 * kp + j;
        int cc = k >> 2, qi = k & 3;
        int tt = qo * 4 + qi;
        v[j] = c_sign[tt] * w[(size_t)c_comp[tt] * O * Ci + (size_t)o * Ci + cc];
    }
    uint32_t wh, wl;
    split2(v[0], v[1], wh, wl);
    hi[idx] = wh; lo[idx] = wl;
}

__global__ void expand_pe_kernel(const float* __restrict__ w, float* __restrict__ out) {
    int idx = blockIdx.x * 256 + threadIdx.x;
    if (idx >= 1024 * 16 * 9) return;
    int kidx = idx % 9; int r = idx / 9;
    int cif = r % 16;   int ocf = r / 16;
    int o = ocf >> 2, qo = ocf & 3, ci = cif >> 2, qi = cif & 3;
    int t = qo * 4 + qi;
    out[idx] = c_sign[t] * w[(size_t)c_comp[t] * (256*4*9) + o * (4*9) + ci * 9 + kidx];
}

// ---------------- split fp32 rows -> packed bf16 planes ----------------
// src: [2*totalPairs][NSP] fp32, out planes: [totalPairs][NSP] u32
__global__ void split_pack(const float* __restrict__ src, uint32_t* __restrict__ hi,
                           uint32_t* __restrict__ lo, long totalPairs) {
    size_t i4 = (size_t)blockIdx.x * 256 + threadIdx.x;
    size_t tot = (size_t)totalPairs * (NSP / 4);
    if (i4 >= tot) return;
    size_t f = i4 / (NSP / 4);
    int n = (int)(i4 % (NSP / 4)) * 4;
    float4 v0 = *(const float4*)(src + (2 * f) * NSP + n);
    float4 v1 = *(const float4*)(src + (2 * f + 1) * NSP + n);
    uint32_t wh[4], wl[4];
    split2(v0.x, v1.x, wh[0], wl[0]);
    split2(v0.y, v1.y, wh[1], wl[1]);
    split2(v0.z, v1.z, wh[2], wl[2]);
    split2(v0.w, v1.w, wh[3], wl[3]);
    *(uint4*)(hi + f * NSP + n) = make_uint4(wh[0], wh[1], wh[2], wh[3]);
    *(uint4*)(lo + f * NSP + n) = make_uint4(wl[0], wl[1], wl[2], wl[3]);
}

// ---------------- bf16x3 mma GEMM, all-plane inputs, cp.async pipelined ----------------
// CTA tile 128x128, chunk = 32 k (16 packed rows), 8 warps (2m x 4n), warp tile 64x32.
#define KPC    16
#define PSTR   136
#define PLANEW (KPC * PSTR)          // 2176 words
#define STAGEW (4 * PLANEW)          // 8704 words
#define GEMM_SMEM_BYTES (2 * STAGEW * 4)   // 69632 B

__global__ __launch_bounds__(256, 2)
void mma_gemm2(const uint32_t* __restrict__ Ah_g, const uint32_t* __restrict__ Al_g,
               const uint32_t* __restrict__ Bh_g, const uint32_t* __restrict__ Bl_g,
               float* __restrict__ Y, int M, int K) {
    extern __shared__ uint32_t sm[];
    uint32_t smb = smem_u32(sm);
    int t = threadIdx.x;
    int wid = t >> 5, lane = t & 31;
    int gid = lane >> 2, tig = lane & 3;
    int wm = (wid >> 2) * 64, wn = (wid & 3) * 32;
    int m0 = blockIdx.y * 128, n0 = blockIdx.x * 128, b = blockIdx.z;
    int KP = K >> 1;
    float* Yb = Y + (size_t)b * M * NSP;

    const uint32_t* base0 = Ah_g + m0;
    const uint32_t* base1 = Al_g + m0;
    const uint32_t* base2 = Bh_g + (size_t)b * KP * NSP + n0;
    const uint32_t* base3 = Bl_g + (size_t)b * KP * NSP + n0;

    int lr = t >> 5;          // 0..7 -> row part
    int lc = (t & 31) * 4;    // word col 0..124

    float c[4][4][4];
    #pragma unroll
    for (int mi = 0; mi < 4; mi++)
        #pragma unroll
        for (int nj = 0; nj < 4; nj++)
            #pragma unroll
            for (int q = 0; q < 4; q++) c[mi][nj][q] = 0.f;

    auto ld_chunk = [&](int kc, int stage) {
        uint32_t sbase = smb + 4u * (stage * STAGEW);
        #pragma unroll
        for (int i = 0; i < 8; i++) {
            const int p = i >> 1;
            int r = 8 * (i & 1) + lr;
            const uint32_t* g;
            if (p == 0)      g = base0 + (size_t)(kc * KPC + r) * M + lc;
            else if (p == 1) g = base1 + (size_t)(kc * KPC + r) * M + lc;
            else if (p == 2) g = base2 + (size_t)(kc * KPC + r) * NSP + lc;
            else             g = base3 + (size_t)(kc * KPC + r) * NSP + lc;
            cp16(sbase + 4u * (p * PLANEW + r * PSTR + lc), g);
        }
        CP_COMMIT();
    };

    ld_chunk(0, 0);

    int T = K / 32;
    for (int kc = 0; kc < T; kc++) {
        CP_WAIT0();
        __syncthreads();
        if (kc + 1 < T) ld_chunk(kc + 1, (kc + 1) & 1);

        const uint32_t* S  = sm + (kc & 1) * STAGEW;
        const uint32_t* Ah = S;
        const uint32_t* Al = S + PLANEW;
        const uint32_t* Bh = S + 2 * PLANEW;
        const uint32_t* Bl = S + 3 * PLANEW;

        #pragma unroll
        for (int st = 0; st < 2; st++) {
            int r0 = (st * 8 + tig) * PSTR, r1 = r0 + 4 * PSTR;
            uint32_t ah[4][4], bh[4][2];
            #pragma unroll
            for (int mi = 0; mi < 4; mi++) {
                int mo = wm + 16 * mi + gid;
                ah[mi][0] = Ah[r0 + mo]; ah[mi][1] = Ah[r0 + mo + 8];
                ah[mi][2] = Ah[r1 + mo]; ah[mi][3] = Ah[r1 + mo + 8];
            }
            #pragma unroll
            for (int nj = 0; nj < 4; nj++) {
                int no = wn + 8 * nj + gid;
                bh[nj][0] = Bh[r0 + no]; bh[nj][1] = Bh[r1 + no];
            }
            #pragma unroll
            for (int mi = 0; mi < 4; mi++)
                #pragma unroll
                for (int nj = 0; nj < 4; nj++) mma16(c[mi][nj], ah[mi], bh[nj]);
            {
                uint32_t bl[4][2];
                #pragma unroll
                for (int nj = 0; nj < 4; nj++) {
                    int no = wn + 8 * nj + gid;
                    bl[nj][0] = Bl[r0 + no]; bl[nj][1] = Bl[r1 + no];
                }
                #pragma unroll
                for (int mi = 0; mi < 4; mi++)
                    #pragma unroll
                    for (int nj = 0; nj < 4; nj++) mma16(c[mi][nj], ah[mi], bl[nj]);
            }
            {
                uint32_t al[4][4];
                #pragma unroll
                for (int mi = 0; mi < 4; mi++) {
                    int mo = wm + 16 * mi + gid;
                    al[mi][0] = Al[r0 + mo]; al[mi][1] = Al[r0 + mo + 8];
                    al[mi][2] = Al[r1 + mo]; al[mi][3] = Al[r1 + mo + 8];
                }
                #pragma unroll
                for (int mi = 0; mi < 4; mi++)
                    #pragma unroll
                    for (int nj = 0; nj < 4; nj++) mma16(c[mi][nj], al[mi], bh[nj]);
            }
        }
    }

    // epilogue: frag rows gid/gid+8, cols 2tig/2tig+1
    #pragma unroll
    for (int mi = 0; mi < 4; mi++) {
        int m = m0 + wm + 16 * mi + gid;
        float* y0 = Yb + (size_t)m * NSP + n0 + wn + 2 * tig;
        float* y1 = y0 + (size_t)8 * NSP;
        #pragma unroll
        for (int nj = 0; nj < 4; nj++) {
            *(float2*)(y0 + nj * 8) = make_float2(c[mi][nj][0], c[mi][nj][1]);
            *(float2*)(y1 + nj * 8) = make_float2(c[mi][nj][2], c[mi][nj][3]);
        }
    }
}

// ---------------- channel attention ----------------
__global__ __launch_bounds__(256)
void attn_kernel(const float* __restrict__ qkv, float* __restrict__ o) {
    int bid = blockIdx.x;
    int b = bid >> 5, h = (bid >> 2) & 7, q = bid & 3;
    const float* base = qkv + (size_t)b * 3072 * NSP;
    const float* Qp = base + ((size_t)(h * 96 + 0)  * 4 + q) * NSP;
    const float* Kp = base + ((size_t)(h * 96 + 32) * 4 + q) * NSP;
    const float* Vp = base + ((size_t)(h * 96 + 64) * 4 + q) * NSP;
    const size_t RS = (size_t)4 * NSP;

    __shared__ float Qs[32][132];
    __shared__ float Ks[32][132];
    __shared__ float Sm[32][32];
    float* sred = &Qs[0][0];

    int t = threadIdx.x;
    int kg = t >> 6, lt = t & 63;
    int c0 = lt >> 3, d0 = lt & 7, kb = kg * 32;

    float s[4][4];
    #pragma unroll
    for (int i = 0; i < 4; i++)
        #pragma unroll
        for (int j = 0; j < 4; j++) s[i][j] = 0.f;

    for (int n0 = 0; n0 < NSP; n0 += 128) {
        #pragma unroll
        for (int i = 0; i < 4; i++) {
            int fl = t + i * 256;
            int r = fl >> 5, cc = fl & 31;
            *(float4*)&Qs[r][cc * 4] = *(const float4*)&Qp[(size_t)r * RS + n0 + cc * 4];
            *(float4*)&Ks[r][cc * 4] = *(const float4*)&Kp[(size_t)r * RS + n0 + cc * 4];
        }
        __syncthreads();
        for (int kk = 0; kk < 32; kk++) {
            float qv[4], kv[4];
            #pragma unroll
            for (int i = 0; i < 4; i++) qv[i] = Qs[c0 + 8 * i][kb + kk];
            #pragma unroll
            for (int j = 0; j < 4; j++) kv[j] = Ks[d0 + 8 * j][kb + kk];
            #pragma unroll
            for (int i = 0; i < 4; i++)
                #pragma unroll
                for (int j = 0; j < 4; j++) s[i][j] += qv[i] * kv[j];
        }
        __syncthreads();
    }
    #pragma unroll
    for (int i = 0; i < 4; i++)
        #pragma unroll
        for (int j = 0; j < 4; j++)
            sred[((size_t)kg * 32 + (c0 + 8 * i)) * 32 + (d0 + 8 * j)] = s[i][j];
    __syncthreads();

    if (t < 32) {
        int c = t;
        float rowv[32];
        float mx = -1e30f;
        #pragma unroll
        for (int d = 0; d < 32; d++) {
            float v = (sred[(0*32 + c)*32 + d] + sred[(1*32 + c)*32 + d] +
                       sred[(2*32 + c)*32 + d] + sred[(3*32 + c)*32 + d]) * SCALE_ATTN;
            rowv[d] = v; mx = fmaxf(mx, v);
        }
        float sum = 0.f;
        #pragma unroll
        for (int d = 0; d < 32; d++) { float e = expf(rowv[d] - mx); rowv[d] = e; sum += e; }
        float inv = 1.f / sum;
        #pragma unroll
        for (int d = 0; d < 32; d++) Sm[c][d] = rowv[d] * inv;
    }
    __syncthreads();

    float* ob = o + (size_t)b * CHF * NSP;
    for (int n = t; n < NSP; n += 256) {
        float v[32];
        #pragma unroll
        for (int d = 0; d < 32; d++) v[d] = Vp[(size_t)d * RS + n];
        #pragma unroll 4
        for (int c = 0; c < 32; c++) {
            float acc = 0.f;
            #pragma unroll
            for (int d = 0; d < 32; d++) acc += Sm[c][d] * v[d];
            ob[((size_t)((h * 32 + c) * 4 + q)) * NSP + n] = acc;
        }
    }
}

// ---------------- grouped 3x3 quaternion conv + residual ----------------
__global__ __launch_bounds__(256)
void peconv_kernel(const float* __restrict__ in, const float* __restrict__ wpe,
                   float* __restrict__ out) {
    extern __shared__ float smem[];
    float* ins = smem;
    float* wts = smem + 19008;

    int ytile = blockIdx.x, g = blockIdx.y, b = blockIdx.z;
    int t = threadIdx.x;

    const float* inb = in + ((size_t)b * CHF + g * 16) * NSP;
    for (int idx = t; idx < 16 * 18 * 66; idx += 256) {
        int xx = idx % 66; int r = idx / 66;
        int yy = r % 18;   int ci = r / 18;
        int gy = ytile * 16 + yy - 1;
        int gx = xx - 1;
        float v = 0.f;
        if (gy >= 0 && gy < 64 && gx >= 0 && gx < 64)
            v = inb[(size_t)ci * NSP + gy * 64 + gx];
        ins[idx] = v;
    }
    for (int idx = t; idx < 16 * 16 * 9; idx += 256) {
        int kidx = idx % 9; int r = idx / 9;
        int ci = r % 16;    int oc = r / 16;
        wts[idx] = wpe[((size_t)(g * 16 + oc)) * (16 * 9) + ci * 9 + kidx];
    }
    __syncthreads();

    int oc = t >> 4, ly = t & 15;
    int gy = ytile * 16 + ly;
    const float* wrow = wts + oc * (16 * 9);
    float* outp = out + ((size_t)b * CHF + g * 16 + oc) * NSP + (size_t)gy * 64;

    for (int x0 = 0; x0 < 64; x0 += 16) {
        float acc[16];
        #pragma unroll
        for (int xi = 0; xi < 16; xi++)
            acc[xi] = ins[(oc * 18 + ly + 1) * 66 + x0 + xi + 1];
        for (int ci = 0; ci < 16; ci++) {
            #pragma unroll
            for (int kh = 0; kh < 3; kh++) {
                const float* ir = &ins[(ci * 18 + ly + kh) * 66 + x0];
                float w0 = wrow[ci * 9 + kh * 3 + 0];
                float w1 = wrow[ci * 9 + kh * 3 + 1];
                float w2 = wrow[ci * 9 + kh * 3 + 2];
                #pragma unroll
                for (int xi = 0; xi < 16; xi++)
                    acc[xi] += w0 * ir[xi] + w1 * ir[xi + 1] + w2 * ir[xi + 2];
            }
        }
        #pragma unroll
        for (int xi = 0; xi < 16; xi++) outp[x0 + xi] = acc[xi];
    }
}

// ---------------- BN stats ----------------
__global__ __launch_bounds__(256)
void stats_kernel(const float* __restrict__ Y, const float* __restrict__ gamma,
                  const float* __restrict__ beta, float* __restrict__ scale,
                  float* __restrict__ shift, int Mch) {
    int ch = blockIdx.x;
    int t = threadIdx.x;
    float s = 0.f, ss = 0.f;
    for (int b = 0; b < 4; b++) {
        const float* p = Y + ((size_t)b * Mch + ch) * NSP;
        for (int n = t; n < NSP; n += 256) { float v = p[n]; s += v; ss += v * v; }
    }
    __shared__ float rs[256], rq[256];
    rs[t] = s; rq[t] = ss;
    __syncthreads();
    for (int off = 128; off > 0; off >>= 1) {
        if (t < off) { rs[t] += rs[t + off]; rq[t] += rq[t + off]; }
        __syncthreads();
    }
    if (t == 0) {
        float cnt = 4.f * NSP;
        float mean = rs[0] / cnt;
        float var = rq[0] / cnt - mean * mean;
        float sc = gamma[ch] * rsqrtf(var + 1e-5f);
        scale[ch] = sc;
        shift[ch] = beta[ch] - mean * sc;
    }
}

// ---------------- fused BN + residual, emitting fp32 + split planes ----------------
__global__ void ew_res_split(const float* __restrict__ X, const float* __restrict__ Yg,
                             const float* __restrict__ sc, const float* __restrict__ sh,
                             float* __restrict__ x1, uint32_t* __restrict__ hi,
                             uint32_t* __restrict__ lo, int Mch) {
    size_t i4 = (size_t)blockIdx.x * 256 + threadIdx.x;
    size_t tot = (size_t)BATCH * (Mch / 2) * (NSP / 4);
    if (i4 >= tot) return;
    size_t f = i4 / (NSP / 4);
    int n = (int)(i4 % (NSP / 4)) * 4;
    int ch0 = (int)((2 * f) % Mch);
    float s0 = sc[ch0], h0 = sh[ch0];
    float s1 = sc[ch0 + 1], h1 = sh[ch0 + 1];
    float4 y0 = *(const float4*)(Yg + (2 * f) * NSP + n);
    float4 y1 = *(const float4*)(Yg + (2 * f + 1) * NSP + n);
    float4 xv0 = *(const float4*)(X + (2 * f) * NSP + n);
    float4 xv1 = *(const float4*)(X + (2 * f + 1) * NSP + n);
    float4 r0, r1;
    r0.x = xv0.x + y0.x * s0 + h0; r0.y = xv0.y + y0.y * s0 + h0;
    r0.z = xv0.z + y0.z * s0 + h0; r0.w = xv0.w + y0.w * s0 + h0;
    r1.x = xv1.x + y1.x * s1 + h1; r1.y = xv1.y + y1.y * s1 + h1;
    r1.z = xv1.z + y1.z * s1 + h1; r1.w = xv1.w + y1.w * s1 + h1;
    *(float4*)(x1 + (2 * f) * NSP + n) = r0;
    *(float4*)(x1 + (2 * f + 1) * NSP + n) = r1;
    uint32_t wh[4], wl[4];
    split2(r0.x, r1.x, wh[0], wl[0]);
    split2(r0.y, r1.y, wh[1], wl[1]);
    split2(r0.z, r1.z, wh[2], wl[2]);
    split2(r0.w, r1.w, wh[3], wl[3]);
    *(uint4*)(hi + f * NSP + n) = make_uint4(wh[0], wh[1], wh[2], wh[3]);
    *(uint4*)(lo + f * NSP + n) = make_uint4(wl[0], wl[1], wl[2], wl[3]);
}

// ---------------- fused BN + relu, emitting split planes only ----------------
__global__ void ew_relu_split(const float* __restrict__ Yg,
                              const float* __restrict__ sc, const float* __restrict__ sh,
                              uint32_t* __restrict__ hi, uint32_t* __restrict__ lo, int Mch) {
    size_t i4 = (size_t)blockIdx.x * 256 + threadIdx.x;
    size_t tot = (size_t)BATCH * (Mch / 2) * (NSP / 4);
    if (i4 >= tot) return;
    size_t f = i4 / (NSP / 4);
    int n = (int)(i4 % (NSP / 4)) * 4;
    int ch0 = (int)((2 * f) % Mch);
    float s0 = sc[ch0], h0 = sh[ch0];
    float s1 = sc[ch0 + 1], h1 = sh[ch0 + 1];
    float4 y0 = *(const float4*)(Yg + (2 * f) * NSP + n);
    float4 y1 = *(const float4*)(Yg + (2 * f + 1) * NSP + n);
    float4 r0, r1;
    r0.x = fmaxf(y0.x * s0 + h0, 0.f); r0.y = fmaxf(y0.y * s0 + h0, 0.f);
    r0.z = fmaxf(y0.z * s0 + h0, 0.f); r0.w = fmaxf(y0.w * s0 + h0, 0.f);
    r1.x = fmaxf(y1.x * s1 + h1, 0.f); r1.y = fmaxf(y1.y * s1 + h1, 0.f);
    r1.z = fmaxf(y1.z * s1 + h1, 0.f); r1.w = fmaxf(y1.w * s1 + h1, 0.f);
    uint32_t wh[4], wl[4];
    split2(r0.x, r1.x, wh[0], wl[0]);
    split2(r0.y, r1.y, wh[1], wl[1]);
    split2(r0.z, r1.z, wh[2], wl[2]);
    split2(r0.w, r1.w, wh[3], wl[3]);
    *(uint4*)(hi + f * NSP + n) = make_uint4(wh[0], wh[1], wh[2], wh[3]);
    *(uint4*)(lo + f * NSP + n) = make_uint4(wl[0], wl[1], wl[2], wl[3]);
}

// ---------------- plain BN + residual (final output) ----------------
__global__ void ew_bn_res_kernel(const float* __restrict__ X, const float* __restrict__ Yg,
                                 const float* __restrict__ sc, const float* __restrict__ sh,
                                 float* __restrict__ out, int Mch) {
    size_t i4 = (size_t)blockIdx.x * 256 + threadIdx.x;
    size_t total4 = (size_t)4 * Mch * NSP / 4;
    if (i4 >= total4) return;
    size_t i = i4 * 4;
    int ch = (int)((i / NSP) % Mch);
    float4 y = *(const float4*)(Yg + i);
    float4 x = *(const float4*)(X + i);
    float s = sc[ch], h = sh[ch];
    float4 r;
    r.x = x.x + y.x * s + h; r.y = x.y + y.y * s + h;
    r.z = x.z + y.z * s + h; r.w = x.w + y.w * s + h;
    *(float4*)(out + i) = r;
}

// ---------------- host launcher ----------------
extern "C" void kernel_launch(void* const* d_in, const int* in_sizes, int n_in,
                              void* d_out, int out_size) {
    const float* x      = (const float*)d_in[0];
    const float* w_qkv  = (const float*)d_in[1];
    const float* w_proj = (const float*)d_in[2];
    const float* w_pe   = (const float*)d_in[3];
    const float* gn     = (const float*)d_in[4];
    const float* bn     = (const float*)d_in[5];
    const float* w_f1   = (const float*)d_in[6];
    const float* gf1    = (const float*)d_in[7];
    const float* bf1    = (const float*)d_in[8];
    const float* w_f2   = (const float*)d_in[9];
    const float* gf2    = (const float*)d_in[10];
    const float* bf2    = (const float*)d_in[11];
    float* out = (float*)d_out;

    void *p;
    uint32_t *qh, *ql, *ph, *pl, *f1h, *f1l, *f2h, *f2l;
    uint32_t *xh, *xl, *o2h, *o2l, *x1h, *x1l, *fbh, *fbl;
    float *wpe, *qkv, *attno, *o2, *tmp, *x1, *sc, *sh;
    cudaGetSymbolAddress(&p, g_wqkv_h);  qh  = (uint32_t*)p;
    cudaGetSymbolAddress(&p, g_wqkv_l);  ql  = (uint32_t*)p;
    cudaGetSymbolAddress(&p, g_wproj_h); ph  = (uint32_t*)p;
    cudaGetSymbolAddress(&p, g_wproj_l); pl  = (uint32_t*)p;
    cudaGetSymbolAddress(&p, g_wf1_h);   f1h = (uint32_t*)p;
    cudaGetSymbolAddress(&p, g_wf1_l);   f1l = (uint32_t*)p;
    cudaGetSymbolAddress(&p, g_wf2_h);   f2h = (uint32_t*)p;
    cudaGetSymbolAddress(&p, g_wf2_l);   f2l = (uint32_t*)p;
    cudaGetSymbolAddress(&p, g_xh);      xh  = (uint32_t*)p;
    cudaGetSymbolAddress(&p, g_xl);      xl  = (uint32_t*)p;
    cudaGetSymbolAddress(&p, g_o2h);     o2h = (uint32_t*)p;
    cudaGetSymbolAddress(&p, g_o2l);     o2l = (uint32_t*)p;
    cudaGetSymbolAddress(&p, g_x1h);     x1h = (uint32_t*)p;
    cudaGetSymbolAddress(&p, g_x1l);     x1l = (uint32_t*)p;
    cudaGetSymbolAddress(&p, g_fbh);     fbh = (uint32_t*)p;
    cudaGetSymbolAddress(&p, g_fbl);     fbl = (uint32_t*)p;
    cudaGetSymbolAddress(&p, g_wpe);     wpe = (float*)p;
    cudaGetSymbolAddress(&p, g_qkv);     qkv = (float*)p;
    cudaGetSymbolAddress(&p, g_attno);   attno = (float*)p;
    cudaGetSymbolAddress(&p, g_o2);      o2  = (float*)p;
    cudaGetSymbolAddress(&p, g_tmp);     tmp = (float*)p;
    cudaGetSymbolAddress(&p, g_x1);      x1  = (float*)p;
    cudaGetSymbolAddress(&p, g_scale);   sc  = (float*)p;
    cudaGetSymbolAddress(&p, g_shift);   sh  = (float*)p;

    cudaFuncSetAttribute(mma_gemm2, cudaFuncAttributeMaxDynamicSharedMemorySize, GEMM_SMEM_BYTES);
    static const int PE_SMEM = (19008 + 2304) * 4;
    cudaFuncSetAttribute(peconv_kernel, cudaFuncAttributeMaxDynamicSharedMemorySize, PE_SMEM);

    // 1. weight expansions -> packed bf16 hi/lo planes
    expand_w_pk<<<(512 * 3072 + 255) / 256, 256>>>(w_qkv,  qh,  ql,  768, 256);
    expand_w_pk<<<(512 * 1024 + 255) / 256, 256>>>(w_proj, ph,  pl,  256, 256);
    expand_w_pk<<<(512 * 2048 + 255) / 256, 256>>>(w_f1,   f1h, f1l, 512, 256);
    expand_w_pk<<<(1024 * 1024 + 255) / 256, 256>>>(w_f2,  f2h, f2l, 256, 512);
    expand_pe_kernel<<<(1024 * 16 * 9 + 255) / 256, 256>>>(w_pe, wpe);

    // 2. split x -> planes, qkv GEMM
    split_pack<<<(int)((size_t)BATCH * 512 * (NSP / 4) / 256), 256>>>(x, xh, xl, BATCH * 512);
    mma_gemm2<<<dim3(32, 24, BATCH), 256, GEMM_SMEM_BYTES>>>(qh, ql, xh, xl, qkv, 3072, 1024);

    // 3. channel attention
    attn_kernel<<<128, 256>>>(qkv, attno);

    // 4. positional conv + residual, split
    peconv_kernel<<<dim3(4, 64, BATCH), 256, PE_SMEM>>>(attno, wpe, o2);
    split_pack<<<(int)((size_t)BATCH * 512 * (NSP / 4) / 256), 256>>>(o2, o2h, o2l, BATCH * 512);

    // 5. proj GEMM + BN + residual -> x1 (+ planes)
    mma_gemm2<<<dim3(32, 8, BATCH), 256, GEMM_SMEM_BYTES>>>(ph, pl, o2h, o2l, tmp, 1024, 1024);
    stats_kernel<<<1024, 256>>>(tmp, gn, bn, sc, sh, 1024);
    ew_res_split<<<(int)((size_t)BATCH * 512 * (NSP / 4) / 256), 256>>>(
        x, tmp, sc, sh, x1, x1h, x1l, 1024);

    // 6. f1 GEMM + BN + relu -> fb planes
    mma_gemm2<<<dim3(32, 16, BATCH), 256, GEMM_SMEM_BYTES>>>(f1h, f1l, x1h, x1l, tmp, 2048, 1024);
    stats_kernel<<<2048, 256>>>(tmp, gf1, bf1, sc, sh, 2048);
    ew_relu_split<<<(int)((size_t)BATCH * 1024 * (NSP / 4) / 256), 256>>>(
        tmp, sc, sh, fbh, fbl, 2048);

    // 7. f2 GEMM + BN + residual -> out
    mma_gemm2<<<dim3(32, 8, BATCH), 256, GEMM_SMEM_BYTES>>>(f2h, f2l, fbh, fbl, tmp, 1024, 2048);
    stats_kernel<<<1024, 256>>>(tmp, gf2, bf2, sc, sh, 1024);
    ew_bn_res_kernel<<<(int)((size_t)4 * 1024 * NSP / 4 / 256), 256>>>(x1, tmp, sc, sh, out, 1024);

    (void)in_sizes; (void)n_in; (void)out_size;
}

// round 6
// speedup vs baseline: 2.3169x; 1.0088x over previous
#include <cuda_runtime.h>
#include <cuda_bf16.h>
#include <cstdint>
#include <cstddef>

// ---------------- problem constants ----------------
#define BATCH 4
#define CHF   1024            // flat channels = C*4
#define NSP   4096            // H*W = 64*64
#define SCALE_ATTN 0.17677669529663687f

// ---------------- scratch ----------------
// packed bf16 k-pair weight planes: [K/2][M] uint32 words (low16 = even k)
__device__ __align__(16) uint32_t g_wqkv_h [512u*3072u];
__device__ __align__(16) uint32_t g_wqkv_l [512u*3072u];
__device__ __align__(16) uint32_t g_wproj_h[512u*1024u];
__device__ __align__(16) uint32_t g_wproj_l[512u*1024u];
__device__ __align__(16) uint32_t g_wf1_h  [512u*2048u];
__device__ __align__(16) uint32_t g_wf1_l  [512u*2048u];
__device__ __align__(16) uint32_t g_wf2_h  [1024u*1024u];
__device__ __align__(16) uint32_t g_wf2_l  [1024u*1024u];
// packed bf16 activation planes: [b][K/2][NSP]
__device__ __align__(16) uint32_t g_xh  [(size_t)BATCH*512*NSP];
__device__ __align__(16) uint32_t g_xl  [(size_t)BATCH*512*NSP];
__device__ __align__(16) uint32_t g_o2h [(size_t)BATCH*512*NSP];
__device__ __align__(16) uint32_t g_o2l [(size_t)BATCH*512*NSP];
__device__ __align__(16) uint32_t g_x1h [(size_t)BATCH*512*NSP];
__device__ __align__(16) uint32_t g_x1l [(size_t)BATCH*512*NSP];
__device__ __align__(16) uint32_t g_fbh [(size_t)BATCH*1024*NSP];
__device__ __align__(16) uint32_t g_fbl [(size_t)BATCH*1024*NSP];

__device__ __align__(16) float g_wpe   [1024u*16u*9u];
__device__ __align__(16) float g_qkv   [(size_t)BATCH*3072*NSP];
__device__ __align__(16) float g_attno [(size_t)BATCH*CHF*NSP];
__device__ __align__(16) float g_o2    [(size_t)BATCH*CHF*NSP];
__device__ __align__(16) float g_tmp   [(size_t)BATCH*2048*NSP];
__device__ __align__(16) float g_x1    [(size_t)BATCH*CHF*NSP];
__device__ __align__(16) float g_spart [128*4*32*32];   // attention partial S
__device__ __align__(16) float g_smx   [128*32*32];     // softmaxed S
__device__ float g_scale [2048];
__device__ float g_shift [2048];

__constant__ int   c_comp[16] = {0,1,2,3, 1,0,3,2, 2,3,0,1, 3,2,1,0};
__constant__ float c_sign[16] = {1.f,-1.f,-1.f,-1.f,
                                 1.f, 1.f, 1.f,-1.f,
                                 1.f,-1.f, 1.f, 1.f,
                                 1.f, 1.f,-1.f, 1.f};

// ---------------- helpers ----------------
__device__ __forceinline__ uint32_t smem_u32(const void* p) {
    uint32_t a;
    asm("{ .reg .u64 t; cvta.to.shared.u64 t, %1; cvt.u32.u64 %0, t; }" : "=r"(a) : "l"(p));
    return a;
}
__device__ __forceinline__ void mma16(float c[4], const uint32_t a[4], const uint32_t b[2]) {
    asm volatile("mma.sync.aligned.m16n8k16.row.col.f32.bf16.bf16.f32 "
        "{%0,%1,%2,%3}, {%4,%5,%6,%7}, {%8,%9}, {%0,%1,%2,%3};"
        : "+f"(c[0]), "+f"(c[1]), "+f"(c[2]), "+f"(c[3])
        : "r"(a[0]), "r"(a[1]), "r"(a[2]), "r"(a[3]), "r"(b[0]), "r"(b[1]));
}
// pack two fp32 into bf16x2 (v0 in low 16), plus residual pack
__device__ __forceinline__ void split2(float v0, float v1, uint32_t& wh, uint32_t& wl) {
    __nv_bfloat162 h = __floats2bfloat162_rn(v0, v1);
    wh = *(uint32_t*)&h;
    float r0 = v0 - __uint_as_float(wh << 16);
    float r1 = v1 - __uint_as_float(wh & 0xFFFF0000u);
    __nv_bfloat162 l = __floats2bfloat162_rn(r0, r1);
    wl = *(uint32_t*)&l;
}
__device__ __forceinline__ void cp16(uint32_t sa, const void* ga) {
    asm volatile("cp.async.cg.shared.global [%0], [%1], 16;" :: "r"(sa), "l"(ga));
}
#define CP_COMMIT() asm volatile("cp.async.commit_group;" ::: "memory")
#define CP_WAIT1()  asm volatile("cp.async.wait_group 1;" ::: "memory")

// ---------------- weight expansion ----------------
__global__ void expand_w_pk(const float* __restrict__ w, uint32_t* __restrict__ hi,
                            uint32_t* __restrict__ lo, int O, int Ci) {
    int M = 4 * O, KP2 = 2 * Ci;
    int idx = blockIdx.x * 256 + threadIdx.x;
    if (idx >= KP2 * M) return;
    int kp = idx / M, m = idx % M;
    int o = m >> 2, qo = m & 3;
    float v[2];
    #pragma unroll
    for (int j = 0; j < 2; j++) {
        int k = 2 * kp + j;
        int cc = k >> 2, qi = k & 3;
        int tt = qo * 4 + qi;
        v[j] = c_sign[tt] * w[(size_t)c_comp[tt] * O * Ci + (size_t)o * Ci + cc];
    }
    uint32_t wh, wl;
    split2(v[0], v[1], wh, wl);
    hi[idx] = wh; lo[idx] = wl;
}

__global__ void expand_pe_kernel(const float* __restrict__ w, float* __restrict__ out) {
    int idx = blockIdx.x * 256 + threadIdx.x;
    if (idx >= 1024 * 16 * 9) return;
    int kidx = idx % 9; int r = idx / 9;
    int cif = r % 16;   int ocf = r / 16;
    int o = ocf >> 2, qo = ocf & 3, ci = cif >> 2, qi = cif & 3;
    int t = qo * 4 + qi;
    out[idx] = c_sign[t] * w[(size_t)c_comp[t] * (256*4*9) + o * (4*9) + ci * 9 + kidx];
}

// ---------------- split fp32 rows -> packed bf16 planes ----------------
__global__ void split_pack(const float* __restrict__ src, uint32_t* __restrict__ hi,
                           uint32_t* __restrict__ lo, long totalPairs) {
    size_t i4 = (size_t)blockIdx.x * 256 + threadIdx.x;
    size_t tot = (size_t)totalPairs * (NSP / 4);
    if (i4 >= tot) return;
    size_t f = i4 / (NSP / 4);
    int n = (int)(i4 % (NSP / 4)) * 4;
    float4 v0 = *(const float4*)(src + (2 * f) * NSP + n);
    float4 v1 = *(const float4*)(src + (2 * f + 1) * NSP + n);
    uint32_t wh[4], wl[4];
    split2(v0.x, v1.x, wh[0], wl[0]);
    split2(v0.y, v1.y, wh[1], wl[1]);
    split2(v0.z, v1.z, wh[2], wl[2]);
    split2(v0.w, v1.w, wh[3], wl[3]);
    *(uint4*)(hi + f * NSP + n) = make_uint4(wh[0], wh[1], wh[2], wh[3]);
    *(uint4*)(lo + f * NSP + n) = make_uint4(wl[0], wl[1], wl[2], wl[3]);
}

// ---------------- bf16x3 mma GEMM, 3-stage cp.async pipeline ----------------
// CTA tile 128x128, chunk = 32 k (16 packed rows), 8 warps (2m x 4n), warp tile 64x32.
#define KPC    16
#define PSTR   136
#define PLANEW (KPC * PSTR)          // 2176 words
#define STAGEW (4 * PLANEW)          // 8704 words
#define GEMM_SMEM_BYTES (3 * STAGEW * 4)   // 104448 B

__global__ __launch_bounds__(256, 2)
void mma_gemm2(const uint32_t* __restrict__ Ah_g, const uint32_t* __restrict__ Al_g,
               const uint32_t* __restrict__ Bh_g, const uint32_t* __restrict__ Bl_g,
               float* __restrict__ Y, int M, int K) {
    extern __shared__ uint32_t sm[];
    uint32_t smb = smem_u32(sm);
    int t = threadIdx.x;
    int wid = t >> 5, lane = t & 31;
    int gid = lane >> 2, tig = lane & 3;
    int wm = (wid >> 2) * 64, wn = (wid & 3) * 32;
    int m0 = blockIdx.y * 128, n0 = blockIdx.x * 128, b = blockIdx.z;
    int KP = K >> 1;
    float* Yb = Y + (size_t)b * M * NSP;

    const uint32_t* base0 = Ah_g + m0;
    const uint32_t* base1 = Al_g + m0;
    const uint32_t* base2 = Bh_g + (size_t)b * KP * NSP + n0;
    const uint32_t* base3 = Bl_g + (size_t)b * KP * NSP + n0;

    int lr = t >> 5;          // 0..7 -> row part
    int lc = (t & 31) * 4;    // word col 0..124

    float c[4][4][4];
    #pragma unroll
    for (int mi = 0; mi < 4; mi++)
        #pragma unroll
        for (int nj = 0; nj < 4; nj++)
            #pragma unroll
            for (int q = 0; q < 4; q++) c[mi][nj][q] = 0.f;

    auto ld_chunk = [&](int kc, int stage) {
        uint32_t sbase = smb + 4u * (stage * STAGEW);
        #pragma unroll
        for (int i = 0; i < 8; i++) {
            const int p = i >> 1;
            int r = 8 * (i & 1) + lr;
            const uint32_t* g;
            if (p == 0)      g = base0 + (size_t)(kc * KPC + r) * M + lc;
            else if (p == 1) g = base1 + (size_t)(kc * KPC + r) * M + lc;
            else if (p == 2) g = base2 + (size_t)(kc * KPC + r) * NSP + lc;
            else             g = base3 + (size_t)(kc * KPC + r) * NSP + lc;
            cp16(sbase + 4u * (p * PLANEW + r * PSTR + lc), g);
        }
        CP_COMMIT();
    };

    int T = K / 32;
    ld_chunk(0, 0);
    ld_chunk(1, 1);

    int stage = 0;
    for (int kc = 0; kc < T; kc++) {
        CP_WAIT1();              // chunk kc complete (one newer group may be pending)
        __syncthreads();         // also guards stage reuse (distance 3)
        if (kc + 2 < T) ld_chunk(kc + 2, (kc + 2) % 3);
        else CP_COMMIT();        // keep group-count invariant for wait_group 1

        const uint32_t* S  = sm + stage * STAGEW;
        const uint32_t* Ah = S;
        const uint32_t* Al = S + PLANEW;
        const uint32_t* Bh = S + 2 * PLANEW;
        const uint32_t* Bl = S + 3 * PLANEW;

        #pragma unroll
        for (int st = 0; st < 2; st++) {
            int r0 = (st * 8 + tig) * PSTR, r1 = r0 + 4 * PSTR;
            uint32_t ah[4][4], bh[4][2];
            #pragma unroll
            for (int mi = 0; mi < 4; mi++) {
                int mo = wm + 16 * mi + gid;
                ah[mi][0] = Ah[r0 + mo]; ah[mi][1] = Ah[r0 + mo + 8];
                ah[mi][2] = Ah[r1 + mo]; ah[mi][3] = Ah[r1 + mo + 8];
            }
            #pragma unroll
            for (int nj = 0; nj < 4; nj++) {
                int no = wn + 8 * nj + gid;
                bh[nj][0] = Bh[r0 + no]; bh[nj][1] = Bh[r1 + no];
            }
            #pragma unroll
            for (int mi = 0; mi < 4; mi++)
                #pragma unroll
                for (int nj = 0; nj < 4; nj++) mma16(c[mi][nj], ah[mi], bh[nj]);
            {
                uint32_t bl[4][2];
                #pragma unroll
                for (int nj = 0; nj < 4; nj++) {
                    int no = wn + 8 * nj + gid;
                    bl[nj][0] = Bl[r0 + no]; bl[nj][1] = Bl[r1 + no];
                }
                #pragma unroll
                for (int mi = 0; mi < 4; mi++)
                    #pragma unroll
                    for (int nj = 0; nj < 4; nj++) mma16(c[mi][nj], ah[mi], bl[nj]);
            }
            {
                uint32_t al[4][4];
                #pragma unroll
                for (int mi = 0; mi < 4; mi++) {
                    int mo = wm + 16 * mi + gid;
                    al[mi][0] = Al[r0 + mo]; al[mi][1] = Al[r0 + mo + 8];
                    al[mi][2] = Al[r1 + mo]; al[mi][3] = Al[r1 + mo + 8];
                }
                #pragma unroll
                for (int mi = 0; mi < 4; mi++)
                    #pragma unroll
                    for (int nj = 0; nj < 4; nj++) mma16(c[mi][nj], al[mi], bh[nj]);
            }
        }
        stage = (stage + 1 == 3) ? 0 : stage + 1;
    }

    // epilogue: frag rows gid/gid+8, cols 2tig/2tig+1
    #pragma unroll
    for (int mi = 0; mi < 4; mi++) {
        int m = m0 + wm + 16 * mi + gid;
        float* y0 = Yb + (size_t)m * NSP + n0 + wn + 2 * tig;
        float* y1 = y0 + (size_t)8 * NSP;
        #pragma unroll
        for (int nj = 0; nj < 4; nj++) {
            *(float2*)(y0 + nj * 8) = make_float2(c[mi][nj][0], c[mi][nj][1]);
            *(float2*)(y1 + nj * 8) = make_float2(c[mi][nj][2], c[mi][nj][3]);
        }
    }
}

// ---------------- attention, split into 3 kernels for parallelism ----------------
// attn_qk: grid (128, 4). Block (bid, quarter) computes partial S over 1024 n.
__global__ __launch_bounds__(256)
void attn_qk(const float* __restrict__ qkv, float* __restrict__ spart) {
    int bid = blockIdx.x, quarter = blockIdx.y;
    int b = bid >> 5, h = (bid >> 2) & 7, q = bid & 3;
    const float* base = qkv + (size_t)b * 3072 * NSP;
    const float* Qp = base + ((size_t)(h * 96 + 0)  * 4 + q) * NSP;
    const float* Kp = base + ((size_t)(h * 96 + 32) * 4 + q) * NSP;
    const size_t RS = (size_t)4 * NSP;

    __shared__ float Qs[32][132];
    __shared__ float Ks[32][132];
    __shared__ float sred[4][32][32];

    int t = threadIdx.x;
    int kg = t >> 6, lt = t & 63;
    int c0 = lt >> 3, d0 = lt & 7, kb = kg * 32;

    float s[4][4];
    #pragma unroll
    for (int i = 0; i < 4; i++)
        #pragma unroll
        for (int j = 0; j < 4; j++) s[i][j] = 0.f;

    int nbeg = quarter * 1024;
    for (int n0 = nbeg; n0 < nbeg + 1024; n0 += 128) {
        #pragma unroll
        for (int i = 0; i < 4; i++) {
            int fl = t + i * 256;
            int r = fl >> 5, cc = fl & 31;
            *(float4*)&Qs[r][cc * 4] = *(const float4*)&Qp[(size_t)r * RS + n0 + cc * 4];
            *(float4*)&Ks[r][cc * 4] = *(const float4*)&Kp[(size_t)r * RS + n0 + cc * 4];
        }
        __syncthreads();
        for (int kk = 0; kk < 32; kk++) {
            float qv[4], kv[4];
            #pragma unroll
            for (int i = 0; i < 4; i++) qv[i] = Qs[c0 + 8 * i][kb + kk];
            #pragma unroll
            for (int j = 0; j < 4; j++) kv[j] = Ks[d0 + 8 * j][kb + kk];
            #pragma unroll
            for (int i = 0; i < 4; i++)
                #pragma unroll
                for (int j = 0; j < 4; j++) s[i][j] += qv[i] * kv[j];
        }
        __syncthreads();
    }
    #pragma unroll
    for (int i = 0; i < 4; i++)
        #pragma unroll
        for (int j = 0; j < 4; j++)
            sred[kg][c0 + 8 * i][d0 + 8 * j] = s[i][j];
    __syncthreads();

    float* sp = spart + ((size_t)bid * 4 + quarter) * 1024;
    for (int e = t; e < 1024; e += 256) {
        int cc = e >> 5, dd = e & 31;
        sp[e] = sred[0][cc][dd] + sred[1][cc][dd] + sred[2][cc][dd] + sred[3][cc][dd];
    }
}

// attn_sm: grid 128, 32 threads. Row softmax over summed quarters.
__global__ void attn_sm(const float* __restrict__ spart, float* __restrict__ smx) {
    int bid = blockIdx.x;
    int c = threadIdx.x;   // 0..31
    const float* sp = spart + (size_t)bid * 4096;
    float rowv[32];
    float mx = -1e30f;
    #pragma unroll
    for (int d = 0; d < 32; d++) {
        float v = (sp[c * 32 + d] + sp[1024 + c * 32 + d] +
                   sp[2048 + c * 32 + d] + sp[3072 + c * 32 + d]) * SCALE_ATTN;
        rowv[d] = v; mx = fmaxf(mx, v);
    }
    float sum = 0.f;
    #pragma unroll
    for (int d = 0; d < 32; d++) { float e = expf(rowv[d] - mx); rowv[d] = e; sum += e; }
    float inv = 1.f / sum;
    #pragma unroll
    for (int d = 0; d < 32; d++) smx[(size_t)bid * 1024 + c * 32 + d] = rowv[d] * inv;
}

// attn_av: grid (128, 4). Block (bid, quarter) computes O slice over 1024 n.
__global__ __launch_bounds__(256)
void attn_av(const float* __restrict__ qkv, const float* __restrict__ smx,
             float* __restrict__ o) {
    int bid = blockIdx.x, quarter = blockIdx.y;
    int b = bid >> 5, h = (bid >> 2) & 7, q = bid & 3;
    const float* Vp = qkv + (size_t)b * 3072 * NSP + ((size_t)(h * 96 + 64) * 4 + q) * NSP;
    const size_t RS = (size_t)4 * NSP;

    __shared__ float Sm[32][32];
    int t = threadIdx.x;
    #pragma unroll
    for (int i = 0; i < 4; i++) {
        int e = t + i * 256;
        Sm[e >> 5][e & 31] = smx[(size_t)bid * 1024 + e];
    }
    __syncthreads();

    float* ob = o + (size_t)b * CHF * NSP;
    int nbeg = quarter * 1024;
    for (int n = nbeg + t; n < nbeg + 1024; n += 256) {
        float v[32];
        #pragma unroll
        for (int d = 0; d < 32; d++) v[d] = Vp[(size_t)d * RS + n];
        #pragma unroll 4
        for (int c = 0; c < 32; c++) {
            float acc = 0.f;
            #pragma unroll
            for (int d = 0; d < 32; d++) acc += Sm[c][d] * v[d];
            ob[((size_t)((h * 32 + c) * 4 + q)) * NSP + n] = acc;
        }
    }
}

// ---------------- grouped 3x3 quaternion conv + residual ----------------
__global__ __launch_bounds__(256)
void peconv_kernel(const float* __restrict__ in, const float* __restrict__ wpe,
                   float* __restrict__ out) {
    extern __shared__ float smem[];
    float* ins = smem;
    float* wts = smem + 19008;

    int ytile = blockIdx.x, g = blockIdx.y, b = blockIdx.z;
    int t = threadIdx.x;

    const float* inb = in + ((size_t)b * CHF + g * 16) * NSP;
    for (int idx = t; idx < 16 * 18 * 66; idx += 256) {
        int xx = idx % 66; int r = idx / 66;
        int yy = r % 18;   int ci = r / 18;
        int gy = ytile * 16 + yy - 1;
        int gx = xx - 1;
        float v = 0.f;
        if (gy >= 0 && gy < 64 && gx >= 0 && gx < 64)
            v = inb[(size_t)ci * NSP + gy * 64 + gx];
        ins[idx] = v;
    }
    for (int idx = t; idx < 16 * 16 * 9; idx += 256) {
        int kidx = idx % 9; int r = idx / 9;
        int ci = r % 16;    int oc = r / 16;
        wts[idx] = wpe[((size_t)(g * 16 + oc)) * (16 * 9) + ci * 9 + kidx];
    }
    __syncthreads();

    int oc = t >> 4, ly = t & 15;
    int gy = ytile * 16 + ly;
    const float* wrow = wts + oc * (16 * 9);
    float* outp = out + ((size_t)b * CHF + g * 16 + oc) * NSP + (size_t)gy * 64;

    for (int x0 = 0; x0 < 64; x0 += 16) {
        float acc[16];
        #pragma unroll
        for (int xi = 0; xi < 16; xi++)
            acc[xi] = ins[(oc * 18 + ly + 1) * 66 + x0 + xi + 1];
        for (int ci = 0; ci < 16; ci++) {
            #pragma unroll
            for (int kh = 0; kh < 3; kh++) {
                const float* ir = &ins[(ci * 18 + ly + kh) * 66 + x0];
                float w0 = wrow[ci * 9 + kh * 3 + 0];
                float w1 = wrow[ci * 9 + kh * 3 + 1];
                float w2 = wrow[ci * 9 + kh * 3 + 2];
                #pragma unroll
                for (int xi = 0; xi < 16; xi++)
                    acc[xi] += w0 * ir[xi] + w1 * ir[xi + 1] + w2 * ir[xi + 2];
            }
        }
        #pragma unroll
        for (int xi = 0; xi < 16; xi++) outp[x0 + xi] = acc[xi];
    }
}

// ---------------- BN stats ----------------
__global__ __launch_bounds__(256)
void stats_kernel(const float* __restrict__ Y, const float* __restrict__ gamma,
                  const float* __restrict__ beta, float* __restrict__ scale,
                  float* __restrict__ shift, int Mch) {
    int ch = blockIdx.x;
    int t = threadIdx.x;
    float s = 0.f, ss = 0.f;
    for (int b = 0; b < 4; b++) {
        const float* p = Y + ((size_t)b * Mch + ch) * NSP;
        for (int n = t; n < NSP; n += 256) { float v = p[n]; s += v; ss += v * v; }
    }
    __shared__ float rs[256], rq[256];
    rs[t] = s; rq[t] = ss;
    __syncthreads();
    for (int off = 128; off > 0; off >>= 1) {
        if (t < off) { rs[t] += rs[t + off]; rq[t] += rq[t + off]; }
        __syncthreads();
    }
    if (t == 0) {
        float cnt = 4.f * NSP;
        float mean = rs[0] / cnt;
        float var = rq[0] / cnt - mean * mean;
        float sc = gamma[ch] * rsqrtf(var + 1e-5f);
        scale[ch] = sc;
        shift[ch] = beta[ch] - mean * sc;
    }
}

// ---------------- fused BN + residual, emitting fp32 + split planes ----------------
__global__ void ew_res_split(const float* __restrict__ X, const float* __restrict__ Yg,
                             const float* __restrict__ sc, const float* __restrict__ sh,
                             float* __restrict__ x1, uint32_t* __restrict__ hi,
                             uint32_t* __restrict__ lo, int Mch) {
    size_t i4 = (size_t)blockIdx.x * 256 + threadIdx.x;
    size_t tot = (size_t)BATCH * (Mch / 2) * (NSP / 4);
    if (i4 >= tot) return;
    size_t f = i4 / (NSP / 4);
    int n = (int)(i4 % (NSP / 4)) * 4;
    int ch0 = (int)((2 * f) % Mch);
    float s0 = sc[ch0], h0 = sh[ch0];
    float s1 = sc[ch0 + 1], h1 = sh[ch0 + 1];
    float4 y0 = *(const float4*)(Yg + (2 * f) * NSP + n);
    float4 y1 = *(const float4*)(Yg + (2 * f + 1) * NSP + n);
    float4 xv0 = *(const float4*)(X + (2 * f) * NSP + n);
    float4 xv1 = *(const float4*)(X + (2 * f + 1) * NSP + n);
    float4 r0, r1;
    r0.x = xv0.x + y0.x * s0 + h0; r0.y = xv0.y + y0.y * s0 + h0;
    r0.z = xv0.z + y0.z * s0 + h0; r0.w = xv0.w + y0.w * s0 + h0;
    r1.x = xv1.x + y1.x * s1 + h1; r1.y = xv1.y + y1.y * s1 + h1;
    r1.z = xv1.z + y1.z * s1 + h1; r1.w = xv1.w + y1.w * s1 + h1;
    *(float4*)(x1 + (2 * f) * NSP + n) = r0;
    *(float4*)(x1 + (2 * f + 1) * NSP + n) = r1;
    uint32_t wh[4], wl[4];
    split2(r0.x, r1.x, wh[0], wl[0]);
    split2(r0.y, r1.y, wh[1], wl[1]);
    split2(r0.z, r1.z, wh[2], wl[2]);
    split2(r0.w, r1.w, wh[3], wl[3]);
    *(uint4*)(hi + f * NSP + n) = make_uint4(wh[0], wh[1], wh[2], wh[3]);
    *(uint4*)(lo + f * NSP + n) = make_uint4(wl[0], wl[1], wl[2], wl[3]);
}

// ---------------- fused BN + relu, emitting split planes only ----------------
__global__ void ew_relu_split(const float* __restrict__ Yg,
                              const float* __restrict__ sc, const float* __restrict__ sh,
                              uint32_t* __restrict__ hi, uint32_t* __restrict__ lo, int Mch) {
    size_t i4 = (size_t)blockIdx.x * 256 + threadIdx.x;
    size_t tot = (size_t)BATCH * (Mch / 2) * (NSP / 4);
    if (i4 >= tot) return;
    size_t f = i4 / (NSP / 4);
    int n = (int)(i4 % (NSP / 4)) * 4;
    int ch0 = (int)((2 * f) % Mch);
    float s0 = sc[ch0], h0 = sh[ch0];
    float s1 = sc[ch0 + 1], h1 = sh[ch0 + 1];
    float4 y0 = *(const float4*)(Yg + (2 * f) * NSP + n);
    float4 y1 = *(const float4*)(Yg + (2 * f + 1) * NSP + n);
    float4 r0, r1;
    r0.x = fmaxf(y0.x * s0 + h0, 0.f); r0.y = fmaxf(y0.y * s0 + h0, 0.f);
    r0.z = fmaxf(y0.z * s0 + h0, 0.f); r0.w = fmaxf(y0.w * s0 + h0, 0.f);
    r1.x = fmaxf(y1.x * s1 + h1, 0.f); r1.y = fmaxf(y1.y * s1 + h1, 0.f);
    r1.z = fmaxf(y1.z * s1 + h1, 0.f); r1.w = fmaxf(y1.w * s1 + h1, 0.f);
    uint32_t wh[4], wl[4];
    split2(r0.x, r1.x, wh[0], wl[0]);
    split2(r0.y, r1.y, wh[1], wl[1]);
    split2(r0.z, r1.z, wh[2], wl[2]);
    split2(r0.w, r1.w, wh[3], wl[3]);
    *(uint4*)(hi + f * NSP + n) = make_uint4(wh[0], wh[1], wh[2], wh[3]);
    *(uint4*)(lo + f * NSP + n) = make_uint4(wl[0], wl[1], wl[2], wl[3]);
}

// ---------------- plain BN + residual (final output) ----------------
__global__ void ew_bn_res_kernel(const float* __restrict__ X, const float* __restrict__ Yg,
                                 const float* __restrict__ sc, const float* __restrict__ sh,
                                 float* __restrict__ out, int Mch) {
    size_t i4 = (size_t)blockIdx.x * 256 + threadIdx.x;
    size_t total4 = (size_t)4 * Mch * NSP / 4;
    if (i4 >= total4) return;
    size_t i = i4 * 4;
    int ch = (int)((i / NSP) % Mch);
    float4 y = *(const float4*)(Yg + i);
    float4 x = *(const float4*)(X + i);
    float s = sc[ch], h = sh[ch];
    float4 r;
    r.x = x.x + y.x * s + h; r.y = x.y + y.y * s + h;
    r.z = x.z + y.z * s + h; r.w = x.w + y.w * s + h;
    *(float4*)(out + i) = r;
}

// ---------------- host launcher ----------------
extern "C" void kernel_launch(void* const* d_in, const int* in_sizes, int n_in,
                              void* d_out, int out_size) {
    const float* x      = (const float*)d_in[0];
    const float* w_qkv  = (const float*)d_in[1];
    const float* w_proj = (const float*)d_in[2];
    const float* w_pe   = (const float*)d_in[3];
    const float* gn     = (const float*)d_in[4];
    const float* bn     = (const float*)d_in[5];
    const float* w_f1   = (const float*)d_in[6];
    const float* gf1    = (const float*)d_in[7];
    const float* bf1    = (const float*)d_in[8];
    const float* w_f2   = (const float*)d_in[9];
    const float* gf2    = (const float*)d_in[10];
    const float* bf2    = (const float*)d_in[11];
    float* out = (float*)d_out;

    void *p;
    uint32_t *qh, *ql, *ph, *pl, *f1h, *f1l, *f2h, *f2l;
    uint32_t *xh, *xl, *o2h, *o2l, *x1h, *x1l, *fbh, *fbl;
    float *wpe, *qkv, *attno, *o2, *tmp, *x1, *sc, *sh, *spart, *smx;
    cudaGetSymbolAddress(&p, g_wqkv_h);  qh  = (uint32_t*)p;
    cudaGetSymbolAddress(&p, g_wqkv_l);  ql  = (uint32_t*)p;
    cudaGetSymbolAddress(&p, g_wproj_h); ph  = (uint32_t*)p;
    cudaGetSymbolAddress(&p, g_wproj_l); pl  = (uint32_t*)p;
    cudaGetSymbolAddress(&p, g_wf1_h);   f1h = (uint32_t*)p;
    cudaGetSymbolAddress(&p, g_wf1_l);   f1l = (uint32_t*)p;
    cudaGetSymbolAddress(&p, g_wf2_h);   f2h = (uint32_t*)p;
    cudaGetSymbolAddress(&p, g_wf2_l);   f2l = (uint32_t*)p;
    cudaGetSymbolAddress(&p, g_xh);      xh  = (uint32_t*)p;
    cudaGetSymbolAddress(&p, g_xl);      xl  = (uint32_t*)p;
    cudaGetSymbolAddress(&p, g_o2h);     o2h = (uint32_t*)p;
    cudaGetSymbolAddress(&p, g_o2l);     o2l = (uint32_t*)p;
    cudaGetSymbolAddress(&p, g_x1h);     x1h = (uint32_t*)p;
    cudaGetSymbolAddress(&p, g_x1l);     x1l = (uint32_t*)p;
    cudaGetSymbolAddress(&p, g_fbh);     fbh = (uint32_t*)p;
    cudaGetSymbolAddress(&p, g_fbl);     fbl = (uint32_t*)p;
    cudaGetSymbolAddress(&p, g_wpe);     wpe = (float*)p;
    cudaGetSymbolAddress(&p, g_qkv);     qkv = (float*)p;
    cudaGetSymbolAddress(&p, g_attno);   attno = (float*)p;
    cudaGetSymbolAddress(&p, g_o2);      o2  = (float*)p;
    cudaGetSymbolAddress(&p, g_tmp);     tmp = (float*)p;
    cudaGetSymbolAddress(&p, g_x1);      x1  = (float*)p;
    cudaGetSymbolAddress(&p, g_scale);   sc  = (float*)p;
    cudaGetSymbolAddress(&p, g_shift);   sh  = (float*)p;
    cudaGetSymbolAddress(&p, g_spart);   spart = (float*)p;
    cudaGetSymbolAddress(&p, g_smx);     smx = (float*)p;

    cudaFuncSetAttribute(mma_gemm2, cudaFuncAttributeMaxDynamicSharedMemorySize, GEMM_SMEM_BYTES);
    static const int PE_SMEM = (19008 + 2304) * 4;
    cudaFuncSetAttribute(peconv_kernel, cudaFuncAttributeMaxDynamicSharedMemorySize, PE_SMEM);

    // 1. weight expansions -> packed bf16 hi/lo planes
    expand_w_pk<<<(512 * 3072 + 255) / 256, 256>>>(w_qkv,  qh,  ql,  768, 256);
    expand_w_pk<<<(512 * 1024 + 255) / 256, 256>>>(w_proj, ph,  pl,  256, 256);
    expand_w_pk<<<(512 * 2048 + 255) / 256, 256>>>(w_f1,   f1h, f1l, 512, 256);
    expand_w_pk<<<(1024 * 1024 + 255) / 256, 256>>>(w_f2,  f2h, f2l, 256, 512);
    expand_pe_kernel<<<(1024 * 16 * 9 + 255) / 256, 256>>>(w_pe, wpe);

    // 2. split x -> planes, qkv GEMM
    split_pack<<<(int)((size_t)BATCH * 512 * (NSP / 4) / 256), 256>>>(x, xh, xl, BATCH * 512);
    mma_gemm2<<<dim3(32, 24, BATCH), 256, GEMM_SMEM_BYTES>>>(qh, ql, xh, xl, qkv, 3072, 1024);

    // 3. channel attention (3-phase, parallel)
    attn_qk<<<dim3(128, 4), 256>>>(qkv, spart);
    attn_sm<<<128, 32>>>(spart, smx);
    attn_av<<<dim3(128, 4), 256>>>(qkv, smx, attno);

    // 4. positional conv + residual, split
    peconv_kernel<<<dim3(4, 64, BATCH), 256, PE_SMEM>>>(attno, wpe, o2);
    split_pack<<<(int)((size_t)BATCH * 512 * (NSP / 4) / 256), 256>>>(o2, o2h, o2l, BATCH * 512);

    // 5. proj GEMM + BN + residual -> x1 (+ planes)
    mma_gemm2<<<dim3(32, 8, BATCH), 256, GEMM_SMEM_BYTES>>>(ph, pl, o2h, o2l, tmp, 1024, 1024);
    stats_kernel<<<1024, 256>>>(tmp, gn, bn, sc, sh, 1024);
    ew_res_split<<<(int)((size_t)BATCH * 512 * (NSP / 4) / 256), 256>>>(
        x, tmp, sc, sh, x1, x1h, x1l, 1024);

    // 6. f1 GEMM + BN + relu -> fb planes
    mma_gemm2<<<dim3(32, 16, BATCH), 256, GEMM_SMEM_BYTES>>>(f1h, f1l, x1h, x1l, tmp, 2048, 1024);
    stats_kernel<<<2048, 256>>>(tmp, gf1, bf1, sc, sh, 2048);
    ew_relu_split<<<(int)((size_t)BATCH * 1024 * (NSP / 4) / 256), 256>>>(
        tmp, sc, sh, fbh, fbl, 2048);

    // 7. f2 GEMM + BN + residual -> out
    mma_gemm2<<<dim3(32, 8, BATCH), 256, GEMM_SMEM_BYTES>>>(f2h, f2l, fbh, fbl, tmp, 1024, 2048);
    stats_kernel<<<1024, 256>>>(tmp, gf2, bf2, sc, sh, 1024);
    ew_bn_res_kernel<<<(int)((size_t)4 * 1024 * NSP / 4 / 256), 256>>>(x1, tmp, sc, sh, out, 1024);

    (void)in_sizes; (void)n_in; (void)out_size;
}

// round 7
// speedup vs baseline: 2.3624x; 1.0196x over previous
#include <cuda_runtime.h>
#include <cuda_bf16.h>
#include <cstdint>
#include <cstddef>

// ---------------- problem constants ----------------
#define BATCH 4
#define CHF   1024            // flat channels = C*4
#define NSP   4096            // H*W = 64*64
#define SCALE_ATTN 0.17677669529663687f

// ---------------- scratch ----------------
// packed bf16 k-pair weight planes: [K/2][M] uint32 words (low16 = even k)
__device__ __align__(16) uint32_t g_wqkv_h [512u*3072u];
__device__ __align__(16) uint32_t g_wqkv_l [512u*3072u];
__device__ __align__(16) uint32_t g_wproj_h[512u*1024u];
__device__ __align__(16) uint32_t g_wproj_l[512u*1024u];
__device__ __align__(16) uint32_t g_wf1_h  [512u*2048u];
__device__ __align__(16) uint32_t g_wf1_l  [512u*2048u];
__device__ __align__(16) uint32_t g_wf2_h  [1024u*1024u];
__device__ __align__(16) uint32_t g_wf2_l  [1024u*1024u];
// packed bf16 activation planes: [b][K/2][NSP]
__device__ __align__(16) uint32_t g_xh  [(size_t)BATCH*512*NSP];
__device__ __align__(16) uint32_t g_xl  [(size_t)BATCH*512*NSP];
__device__ __align__(16) uint32_t g_o2h [(size_t)BATCH*512*NSP];
__device__ __align__(16) uint32_t g_o2l [(size_t)BATCH*512*NSP];
__device__ __align__(16) uint32_t g_x1h [(size_t)BATCH*512*NSP];
__device__ __align__(16) uint32_t g_x1l [(size_t)BATCH*512*NSP];
__device__ __align__(16) uint32_t g_fbh [(size_t)BATCH*1024*NSP];
__device__ __align__(16) uint32_t g_fbl [(size_t)BATCH*1024*NSP];

__device__ __align__(16) float g_wpe   [1024u*16u*9u];
__device__ __align__(16) float g_qkv   [(size_t)BATCH*3072*NSP];
__device__ __align__(16) float g_attno [(size_t)BATCH*CHF*NSP];
__device__ __align__(16) float g_tmp   [(size_t)BATCH*2048*NSP];
__device__ __align__(16) float g_x1    [(size_t)BATCH*CHF*NSP];
__device__ __align__(16) float g_spart [128*4*32*32];   // attention partial S
__device__ __align__(16) float g_pstat [3*2*2048];      // per-stage psum/psqr

__constant__ int   c_comp[16] = {0,1,2,3, 1,0,3,2, 2,3,0,1, 3,2,1,0};
__constant__ float c_sign[16] = {1.f,-1.f,-1.f,-1.f,
                                 1.f, 1.f, 1.f,-1.f,
                                 1.f,-1.f, 1.f, 1.f,
                                 1.f, 1.f,-1.f, 1.f};

// ---------------- helpers ----------------
__device__ __forceinline__ uint32_t smem_u32(const void* p) {
    uint32_t a;
    asm("{ .reg .u64 t; cvta.to.shared.u64 t, %1; cvt.u32.u64 %0, t; }" : "=r"(a) : "l"(p));
    return a;
}
__device__ __forceinline__ void mma16(float c[4], const uint32_t a[4], const uint32_t b[2]) {
    asm volatile("mma.sync.aligned.m16n8k16.row.col.f32.bf16.bf16.f32 "
        "{%0,%1,%2,%3}, {%4,%5,%6,%7}, {%8,%9}, {%0,%1,%2,%3};"
        : "+f"(c[0]), "+f"(c[1]), "+f"(c[2]), "+f"(c[3])
        : "r"(a[0]), "r"(a[1]), "r"(a[2]), "r"(a[3]), "r"(b[0]), "r"(b[1]));
}
// pack two fp32 into bf16x2 (v0 in low 16), plus residual pack
__device__ __forceinline__ void split2(float v0, float v1, uint32_t& wh, uint32_t& wl) {
    __nv_bfloat162 h = __floats2bfloat162_rn(v0, v1);
    wh = *(uint32_t*)&h;
    float r0 = v0 - __uint_as_float(wh << 16);
    float r1 = v1 - __uint_as_float(wh & 0xFFFF0000u);
    __nv_bfloat162 l = __floats2bfloat162_rn(r0, r1);
    wl = *(uint32_t*)&l;
}
__device__ __forceinline__ void cp16(uint32_t sa, const void* ga) {
    asm volatile("cp.async.cg.shared.global [%0], [%1], 16;" :: "r"(sa), "l"(ga));
}
#define CP_COMMIT() asm volatile("cp.async.commit_group;" ::: "memory")
#define CP_WAIT1()  asm volatile("cp.async.wait_group 1;" ::: "memory")

// inline BN coeff from fused partials
__device__ __forceinline__ void bn_coeff(const float* psum, const float* psqr,
                                         const float* gamma, const float* beta,
                                         int ch, float& s, float& h) {
    const float ic = 1.f / 16384.f;
    float mean = psum[ch] * ic;
    float var = psqr[ch] * ic - mean * mean;
    s = gamma[ch] * rsqrtf(var + 1e-5f);
    h = beta[ch] - mean * s;
}

// ---------------- weight expansion ----------------
__global__ void expand_w_pk(const float* __restrict__ w, uint32_t* __restrict__ hi,
                            uint32_t* __restrict__ lo, int O, int Ci) {
    int M = 4 * O, KP2 = 2 * Ci;
    int idx = blockIdx.x * 256 + threadIdx.x;
    if (idx >= KP2 * M) return;
    int kp = idx / M, m = idx % M;
    int o = m >> 2, qo = m & 3;
    float v[2];
    #pragma unroll
    for (int j = 0; j < 2; j++) {
        int k = 2 * kp + j;
        int cc = k >> 2, qi = k & 3;
        int tt = qo * 4 + qi;
        v[j] = c_sign[tt] * w[(size_t)c_comp[tt] * O * Ci + (size_t)o * Ci + cc];
    }
    uint32_t wh, wl;
    split2(v[0], v[1], wh, wl);
    hi[idx] = wh; lo[idx] = wl;
}

__global__ void expand_pe_kernel(const float* __restrict__ w, float* __restrict__ out) {
    int idx = blockIdx.x * 256 + threadIdx.x;
    if (idx >= 1024 * 16 * 9) return;
    int kidx = idx % 9; int r = idx / 9;
    int cif = r % 16;   int ocf = r / 16;
    int o = ocf >> 2, qo = ocf & 3, ci = cif >> 2, qi = cif & 3;
    int t = qo * 4 + qi;
    out[idx] = c_sign[t] * w[(size_t)c_comp[t] * (256*4*9) + o * (4*9) + ci * 9 + kidx];
}

// ---------------- split fp32 rows -> packed bf16 planes ----------------
__global__ void split_pack(const float* __restrict__ src, uint32_t* __restrict__ hi,
                           uint32_t* __restrict__ lo, long totalPairs) {
    size_t i4 = (size_t)blockIdx.x * 256 + threadIdx.x;
    size_t tot = (size_t)totalPairs * (NSP / 4);
    if (i4 >= tot) return;
    size_t f = i4 / (NSP / 4);
    int n = (int)(i4 % (NSP / 4)) * 4;
    float4 v0 = *(const float4*)(src + (2 * f) * NSP + n);
    float4 v1 = *(const float4*)(src + (2 * f + 1) * NSP + n);
    uint32_t wh[4], wl[4];
    split2(v0.x, v1.x, wh[0], wl[0]);
    split2(v0.y, v1.y, wh[1], wl[1]);
    split2(v0.z, v1.z, wh[2], wl[2]);
    split2(v0.w, v1.w, wh[3], wl[3]);
    *(uint4*)(hi + f * NSP + n) = make_uint4(wh[0], wh[1], wh[2], wh[3]);
    *(uint4*)(lo + f * NSP + n) = make_uint4(wl[0], wl[1], wl[2], wl[3]);
}

// ---------------- bf16x3 mma GEMM, 3-stage cp.async, optional fused BN stats ----------------
#define KPC    16
#define PSTR   136
#define PLANEW (KPC * PSTR)          // 2176 words
#define STAGEW (4 * PLANEW)          // 8704 words
#define GEMM_SMEM_BYTES (3 * STAGEW * 4)   // 104448 B

template<bool STATS>
__global__ __launch_bounds__(256, 2)
void mma_gemm2(const uint32_t* __restrict__ Ah_g, const uint32_t* __restrict__ Al_g,
               const uint32_t* __restrict__ Bh_g, const uint32_t* __restrict__ Bl_g,
               float* __restrict__ Y, float* psum, float* psqr, int M, int K) {
    extern __shared__ uint32_t sm[];
    uint32_t smb = smem_u32(sm);
    int t = threadIdx.x;
    int wid = t >> 5, lane = t & 31;
    int gid = lane >> 2, tig = lane & 3;
    int wm = (wid >> 2) * 64, wn = (wid & 3) * 32;
    int m0 = blockIdx.y * 128, n0 = blockIdx.x * 128, b = blockIdx.z;
    int KP = K >> 1;
    float* Yb = Y + (size_t)b * M * NSP;

    const uint32_t* base0 = Ah_g + m0;
    const uint32_t* base1 = Al_g + m0;
    const uint32_t* base2 = Bh_g + (size_t)b * KP * NSP + n0;
    const uint32_t* base3 = Bl_g + (size_t)b * KP * NSP + n0;

    int lr = t >> 5;          // 0..7 -> row part
    int lc = (t & 31) * 4;    // word col 0..124

    float c[4][4][4];
    #pragma unroll
    for (int mi = 0; mi < 4; mi++)
        #pragma unroll
        for (int nj = 0; nj < 4; nj++)
            #pragma unroll
            for (int q = 0; q < 4; q++) c[mi][nj][q] = 0.f;

    auto ld_chunk = [&](int kc, int stage) {
        uint32_t sbase = smb + 4u * (stage * STAGEW);
        #pragma unroll
        for (int i = 0; i < 8; i++) {
            const int p = i >> 1;
            int r = 8 * (i & 1) + lr;
            const uint32_t* g;
            if (p == 0)      g = base0 + (size_t)(kc * KPC + r) * M + lc;
            else if (p == 1) g = base1 + (size_t)(kc * KPC + r) * M + lc;
            else if (p == 2) g = base2 + (size_t)(kc * KPC + r) * NSP + lc;
            else             g = base3 + (size_t)(kc * KPC + r) * NSP + lc;
            cp16(sbase + 4u * (p * PLANEW + r * PSTR + lc), g);
        }
        CP_COMMIT();
    };

    int T = K / 32;
    ld_chunk(0, 0);
    ld_chunk(1, 1);

    int stage = 0;
    for (int kc = 0; kc < T; kc++) {
        CP_WAIT1();
        __syncthreads();
        if (kc + 2 < T) ld_chunk(kc + 2, (kc + 2) % 3);
        else CP_COMMIT();

        const uint32_t* S  = sm + stage * STAGEW;
        const uint32_t* Ah = S;
        const uint32_t* Al = S + PLANEW;
        const uint32_t* Bh = S + 2 * PLANEW;
        const uint32_t* Bl = S + 3 * PLANEW;

        #pragma unroll
        for (int st = 0; st < 2; st++) {
            int r0 = (st * 8 + tig) * PSTR, r1 = r0 + 4 * PSTR;
            uint32_t ah[4][4], bh[4][2];
            #pragma unroll
            for (int mi = 0; mi < 4; mi++) {
                int mo = wm + 16 * mi + gid;
                ah[mi][0] = Ah[r0 + mo]; ah[mi][1] = Ah[r0 + mo + 8];
                ah[mi][2] = Ah[r1 + mo]; ah[mi][3] = Ah[r1 + mo + 8];
            }
            #pragma unroll
            for (int nj = 0; nj < 4; nj++) {
                int no = wn + 8 * nj + gid;
                bh[nj][0] = Bh[r0 + no]; bh[nj][1] = Bh[r1 + no];
            }
            #pragma unroll
            for (int mi = 0; mi < 4; mi++)
                #pragma unroll
                for (int nj = 0; nj < 4; nj++) mma16(c[mi][nj], ah[mi], bh[nj]);
            {
                uint32_t bl[4][2];
                #pragma unroll
                for (int nj = 0; nj < 4; nj++) {
                    int no = wn + 8 * nj + gid;
                    bl[nj][0] = Bl[r0 + no]; bl[nj][1] = Bl[r1 + no];
                }
                #pragma unroll
                for (int mi = 0; mi < 4; mi++)
                    #pragma unroll
                    for (int nj = 0; nj < 4; nj++) mma16(c[mi][nj], ah[mi], bl[nj]);
            }
            {
                uint32_t al[4][4];
                #pragma unroll
                for (int mi = 0; mi < 4; mi++) {
                    int mo = wm + 16 * mi + gid;
                    al[mi][0] = Al[r0 + mo]; al[mi][1] = Al[r0 + mo + 8];
                    al[mi][2] = Al[r1 + mo]; al[mi][3] = Al[r1 + mo + 8];
                }
                #pragma unroll
                for (int mi = 0; mi < 4; mi++)
                    #pragma unroll
                    for (int nj = 0; nj < 4; nj++) mma16(c[mi][nj], al[mi], bh[nj]);
            }
        }
        stage = (stage + 1 == 3) ? 0 : stage + 1;
    }

    // epilogue: frag rows gid/gid+8, cols 2tig/2tig+1
    #pragma unroll
    for (int mi = 0; mi < 4; mi++) {
        int m = m0 + wm + 16 * mi + gid;
        float* y0 = Yb + (size_t)m * NSP + n0 + wn + 2 * tig;
        float* y1 = y0 + (size_t)8 * NSP;
        #pragma unroll
        for (int nj = 0; nj < 4; nj++) {
            *(float2*)(y0 + nj * 8) = make_float2(c[mi][nj][0], c[mi][nj][1]);
            *(float2*)(y1 + nj * 8) = make_float2(c[mi][nj][2], c[mi][nj][3]);
        }
    }

    if (STATS) {
        __syncthreads();                 // pipeline smem no longer read; reuse
        float* ssum = (float*)sm;        // [128]
        float* ssq  = (float*)sm + 128;  // [128]
        if (t < 128) { ssum[t] = 0.f; ssq[t] = 0.f; }
        __syncthreads();
        #pragma unroll
        for (int mi = 0; mi < 4; mi++) {
            float s0 = 0.f, q0 = 0.f, s1 = 0.f, q1 = 0.f;
            #pragma unroll
            for (int nj = 0; nj < 4; nj++) {
                s0 += c[mi][nj][0] + c[mi][nj][1];
                q0 += c[mi][nj][0] * c[mi][nj][0] + c[mi][nj][1] * c[mi][nj][1];
                s1 += c[mi][nj][2] + c[mi][nj][3];
                q1 += c[mi][nj][2] * c[mi][nj][2] + c[mi][nj][3] * c[mi][nj][3];
            }
            #pragma unroll
            for (int off = 1; off <= 2; off <<= 1) {
                s0 += __shfl_xor_sync(0xffffffffu, s0, off);
                q0 += __shfl_xor_sync(0xffffffffu, q0, off);
                s1 += __shfl_xor_sync(0xffffffffu, s1, off);
                q1 += __shfl_xor_sync(0xffffffffu, q1, off);
            }
            if (tig == 0) {
                int r = wm + 16 * mi + gid;
                atomicAdd(&ssum[r], s0);     atomicAdd(&ssq[r], q0);
                atomicAdd(&ssum[r + 8], s1); atomicAdd(&ssq[r + 8], q1);
            }
        }
        __syncthreads();
        if (t < 128) {
            atomicAdd(&psum[m0 + t], ssum[t]);
            atomicAdd(&psqr[m0 + t], ssq[t]);
        }
    }
}

// ---------------- attention ----------------
__global__ __launch_bounds__(256)
void attn_qk(const float* __restrict__ qkv, float* __restrict__ spart) {
    int bid = blockIdx.x, quarter = blockIdx.y;
    int b = bid >> 5, h = (bid >> 2) & 7, q = bid & 3;
    const float* base = qkv + (size_t)b * 3072 * NSP;
    const float* Qp = base + ((size_t)(h * 96 + 0)  * 4 + q) * NSP;
    const float* Kp = base + ((size_t)(h * 96 + 32) * 4 + q) * NSP;
    const size_t RS = (size_t)4 * NSP;

    __shared__ float Qs[32][132];
    __shared__ float Ks[32][132];
    __shared__ float sred[4][32][32];

    int t = threadIdx.x;
    int kg = t >> 6, lt = t & 63;
    int c0 = lt >> 3, d0 = lt & 7, kb = kg * 32;

    float s[4][4];
    #pragma unroll
    for (int i = 0; i < 4; i++)
        #pragma unroll
        for (int j = 0; j < 4; j++) s[i][j] = 0.f;

    int nbeg = quarter * 1024;
    for (int n0 = nbeg; n0 < nbeg + 1024; n0 += 128) {
        #pragma unroll
        for (int i = 0; i < 4; i++) {
            int fl = t + i * 256;
            int r = fl >> 5, cc = fl & 31;
            *(float4*)&Qs[r][cc * 4] = *(const float4*)&Qp[(size_t)r * RS + n0 + cc * 4];
            *(float4*)&Ks[r][cc * 4] = *(const float4*)&Kp[(size_t)r * RS + n0 + cc * 4];
        }
        __syncthreads();
        for (int kk = 0; kk < 32; kk++) {
            float qv[4], kv[4];
            #pragma unroll
            for (int i = 0; i < 4; i++) qv[i] = Qs[c0 + 8 * i][kb + kk];
            #pragma unroll
            for (int j = 0; j < 4; j++) kv[j] = Ks[d0 + 8 * j][kb + kk];
            #pragma unroll
            for (int i = 0; i < 4; i++)
                #pragma unroll
                for (int j = 0; j < 4; j++) s[i][j] += qv[i] * kv[j];
        }
        __syncthreads();
    }
    #pragma unroll
    for (int i = 0; i < 4; i++)
        #pragma unroll
        for (int j = 0; j < 4; j++)
            sred[kg][c0 + 8 * i][d0 + 8 * j] = s[i][j];
    __syncthreads();

    float* sp = spart + ((size_t)bid * 4 + quarter) * 1024;
    for (int e = t; e < 1024; e += 256) {
        int cc = e >> 5, dd = e & 31;
        sp[e] = sred[0][cc][dd] + sred[1][cc][dd] + sred[2][cc][dd] + sred[3][cc][dd];
    }
}

// attn_av with inline softmax (each of 4 quarter-blocks recomputes the 32x32 softmax; cheap)
__global__ __launch_bounds__(256)
void attn_av(const float* __restrict__ qkv, const float* __restrict__ spart,
             float* __restrict__ o) {
    int bid = blockIdx.x, quarter = blockIdx.y;
    int b = bid >> 5, h = (bid >> 2) & 7, q = bid & 3;
    const float* Vp = qkv + (size_t)b * 3072 * NSP + ((size_t)(h * 96 + 64) * 4 + q) * NSP;
    const size_t RS = (size_t)4 * NSP;

    __shared__ float Sm[32][32];
    int t = threadIdx.x;
    if (t < 32) {
        int c = t;
        const float* sp = spart + (size_t)bid * 4096;
        float rowv[32];
        float mx = -1e30f;
        #pragma unroll
        for (int d = 0; d < 32; d++) {
            float v = (sp[c * 32 + d] + sp[1024 + c * 32 + d] +
                       sp[2048 + c * 32 + d] + sp[3072 + c * 32 + d]) * SCALE_ATTN;
            rowv[d] = v; mx = fmaxf(mx, v);
        }
        float sum = 0.f;
        #pragma unroll
        for (int d = 0; d < 32; d++) { float e = expf(rowv[d] - mx); rowv[d] = e; sum += e; }
        float inv = 1.f / sum;
        #pragma unroll
        for (int d = 0; d < 32; d++) Sm[c][d] = rowv[d] * inv;
    }
    __syncthreads();

    float* ob = o + (size_t)b * CHF * NSP;
    int nbeg = quarter * 1024;
    for (int n = nbeg + t; n < nbeg + 1024; n += 256) {
        float v[32];
        #pragma unroll
        for (int d = 0; d < 32; d++) v[d] = Vp[(size_t)d * RS + n];
        #pragma unroll 4
        for (int c = 0; c < 32; c++) {
            float acc = 0.f;
            #pragma unroll
            for (int d = 0; d < 32; d++) acc += Sm[c][d] * v[d];
            ob[((size_t)((h * 32 + c) * 4 + q)) * NSP + n] = acc;
        }
    }
}

// ---------------- grouped 3x3 quaternion conv + residual -> bf16 planes directly ----------------
__global__ __launch_bounds__(256)
void peconv_kernel(const float* __restrict__ in, const float* __restrict__ wpe,
                   uint32_t* __restrict__ hi, uint32_t* __restrict__ lo) {
    extern __shared__ float smem[];
    float* ins = smem;
    float* wts = smem + 19008;

    int ytile = blockIdx.x, g = blockIdx.y, b = blockIdx.z;
    int t = threadIdx.x;
    int lane = t & 31, w = t >> 5;

    const float* inb = in + ((size_t)b * CHF + g * 16) * NSP;
    for (int idx = t; idx < 16 * 18 * 66; idx += 256) {
        int xx = idx % 66; int r = idx / 66;
        int yy = r % 18;   int ci = r / 18;
        int gy = ytile * 16 + yy - 1;
        int gx = xx - 1;
        float v = 0.f;
        if (gy >= 0 && gy < 64 && gx >= 0 && gx < 64)
            v = inb[(size_t)ci * NSP + gy * 64 + gx];
        ins[idx] = v;
    }
    for (int idx = t; idx < 16 * 16 * 9; idx += 256) {
        int kidx = idx % 9; int r = idx / 9;
        int ci = r % 16;    int oc = r / 16;
        wts[idx] = wpe[((size_t)(g * 16 + oc)) * (16 * 9) + ci * 9 + kidx];
    }
    __syncthreads();

    int oc = t >> 4, ly = t & 15;
    int gy = ytile * 16 + ly;
    const float* wrow = wts + oc * (16 * 9);
    // channel pair index for even-oc lanes (lane<16): f = g*8 + w
    size_t fbase = ((size_t)b * 512 + g * 8 + w) * NSP + (size_t)gy * 64;

    for (int x0 = 0; x0 < 64; x0 += 16) {
        float acc[16];
        #pragma unroll
        for (int xi = 0; xi < 16; xi++)
            acc[xi] = ins[(oc * 18 + ly + 1) * 66 + x0 + xi + 1];   // residual
        for (int ci = 0; ci < 16; ci++) {
            #pragma unroll
            for (int kh = 0; kh < 3; kh++) {
                const float* ir = &ins[(ci * 18 + ly + kh) * 66 + x0];
                float w0 = wrow[ci * 9 + kh * 3 + 0];
                float w1 = wrow[ci * 9 + kh * 3 + 1];
                float w2 = wrow[ci * 9 + kh * 3 + 2];
                #pragma unroll
                for (int xi = 0; xi < 16; xi++)
                    acc[xi] += w0 * ir[xi] + w1 * ir[xi + 1] + w2 * ir[xi + 2];
            }
        }
        // pair channels (2f, 2f+1) live at lanes l and l+16 (same ly); split+store planes
        #pragma unroll
        for (int xi = 0; xi < 16; xi++) {
            float other = __shfl_xor_sync(0xffffffffu, acc[xi], 16);
            if (lane < 16) {
                uint32_t wh, wl;
                split2(acc[xi], other, wh, wl);
                hi[fbase + x0 + xi] = wh;
                lo[fbase + x0 + xi] = wl;
            }
        }
    }
}

// ---------------- fused BN(inline coeff) + residual, emitting fp32 + split planes ----------------
__global__ void ew_res_split(const float* __restrict__ X, const float* __restrict__ Yg,
                             const float* __restrict__ psum, const float* __restrict__ psqr,
                             const float* __restrict__ gamma, const float* __restrict__ beta,
                             float* __restrict__ x1, uint32_t* __restrict__ hi,
                             uint32_t* __restrict__ lo, int Mch) {
    size_t i4 = (size_t)blockIdx.x * 256 + threadIdx.x;
    size_t tot = (size_t)BATCH * (Mch / 2) * (NSP / 4);
    if (i4 >= tot) return;
    size_t f = i4 / (NSP / 4);
    int n = (int)(i4 % (NSP / 4)) * 4;
    int ch0 = (int)((2 * f) % Mch);
    float s0, h0, s1, h1;
    bn_coeff(psum, psqr, gamma, beta, ch0, s0, h0);
    bn_coeff(psum, psqr, gamma, beta, ch0 + 1, s1, h1);
    float4 y0 = *(const float4*)(Yg + (2 * f) * NSP + n);
    float4 y1 = *(const float4*)(Yg + (2 * f + 1) * NSP + n);
    float4 xv0 = *(const float4*)(X + (2 * f) * NSP + n);
    float4 xv1 = *(const float4*)(X + (2 * f + 1) * NSP + n);
    float4 r0, r1;
    r0.x = xv0.x + y0.x * s0 + h0; r0.y = xv0.y + y0.y * s0 + h0;
    r0.z = xv0.z + y0.z * s0 + h0; r0.w = xv0.w + y0.w * s0 + h0;
    r1.x = xv1.x + y1.x * s1 + h1; r1.y = xv1.y + y1.y * s1 + h1;
    r1.z = xv1.z + y1.z * s1 + h1; r1.w = xv1.w + y1.w * s1 + h1;
    *(float4*)(x1 + (2 * f) * NSP + n) = r0;
    *(float4*)(x1 + (2 * f + 1) * NSP + n) = r1;
    uint32_t wh[4], wl[4];
    split2(r0.x, r1.x, wh[0], wl[0]);
    split2(r0.y, r1.y, wh[1], wl[1]);
    split2(r0.z, r1.z, wh[2], wl[2]);
    split2(r0.w, r1.w, wh[3], wl[3]);
    *(uint4*)(hi + f * NSP + n) = make_uint4(wh[0], wh[1], wh[2], wh[3]);
    *(uint4*)(lo + f * NSP + n) = make_uint4(wl[0], wl[1], wl[2], wl[3]);
}

// ---------------- fused BN(inline) + relu, emitting split planes only ----------------
__global__ void ew_relu_split(const float* __restrict__ Yg,
                              const float* __restrict__ psum, const float* __restrict__ psqr,
                              const float* __restrict__ gamma, const float* __restrict__ beta,
                              uint32_t* __restrict__ hi, uint32_t* __restrict__ lo, int Mch) {
    size_t i4 = (size_t)blockIdx.x * 256 + threadIdx.x;
    size_t tot = (size_t)BATCH * (Mch / 2) * (NSP / 4);
    if (i4 >= tot) return;
    size_t f = i4 / (NSP / 4);
    int n = (int)(i4 % (NSP / 4)) * 4;
    int ch0 = (int)((2 * f) % Mch);
    float s0, h0, s1, h1;
    bn_coeff(psum, psqr, gamma, beta, ch0, s0, h0);
    bn_coeff(psum, psqr, gamma, beta, ch0 + 1, s1, h1);
    float4 y0 = *(const float4*)(Yg + (2 * f) * NSP + n);
    float4 y1 = *(const float4*)(Yg + (2 * f + 1) * NSP + n);
    float4 r0, r1;
    r0.x = fmaxf(y0.x * s0 + h0, 0.f); r0.y = fmaxf(y0.y * s0 + h0, 0.f);
    r0.z = fmaxf(y0.z * s0 + h0, 0.f); r0.w = fmaxf(y0.w * s0 + h0, 0.f);
    r1.x = fmaxf(y1.x * s1 + h1, 0.f); r1.y = fmaxf(y1.y * s1 + h1, 0.f);
    r1.z = fmaxf(y1.z * s1 + h1, 0.f); r1.w = fmaxf(y1.w * s1 + h1, 0.f);
    uint32_t wh[4], wl[4];
    split2(r0.x, r1.x, wh[0], wl[0]);
    split2(r0.y, r1.y, wh[1], wl[1]);
    split2(r0.z, r1.z, wh[2], wl[2]);
    split2(r0.w, r1.w, wh[3], wl[3]);
    *(uint4*)(hi + f * NSP + n) = make_uint4(wh[0], wh[1], wh[2], wh[3]);
    *(uint4*)(lo + f * NSP + n) = make_uint4(wl[0], wl[1], wl[2], wl[3]);
}

// ---------------- plain BN(inline) + residual (final output) ----------------
__global__ void ew_bn_res_kernel(const float* __restrict__ X, const float* __restrict__ Yg,
                                 const float* __restrict__ psum, const float* __restrict__ psqr,
                                 const float* __restrict__ gamma, const float* __restrict__ beta,
                                 float* __restrict__ out, int Mch) {
    size_t i4 = (size_t)blockIdx.x * 256 + threadIdx.x;
    size_t total4 = (size_t)4 * Mch * NSP / 4;
    if (i4 >= total4) return;
    size_t i = i4 * 4;
    int ch = (int)((i / NSP) % Mch);
    float s, h;
    bn_coeff(psum, psqr, gamma, beta, ch, s, h);
    float4 y = *(const float4*)(Yg + i);
    float4 x = *(const float4*)(X + i);
    float4 r;
    r.x = x.x + y.x * s + h; r.y = x.y + y.y * s + h;
    r.z = x.z + y.z * s + h; r.w = x.w + y.w * s + h;
    *(float4*)(out + i) = r;
}

// ---------------- host launcher ----------------
extern "C" void kernel_launch(void* const* d_in, const int* in_sizes, int n_in,
                              void* d_out, int out_size) {
    const float* x      = (const float*)d_in[0];
    const float* w_qkv  = (const float*)d_in[1];
    const float* w_proj = (const float*)d_in[2];
    const float* w_pe   = (const float*)d_in[3];
    const float* gn     = (const float*)d_in[4];
    const float* bn     = (const float*)d_in[5];
    const float* w_f1   = (const float*)d_in[6];
    const float* gf1    = (const float*)d_in[7];
    const float* bf1    = (const float*)d_in[8];
    const float* w_f2   = (const float*)d_in[9];
    const float* gf2    = (const float*)d_in[10];
    const float* bf2    = (const float*)d_in[11];
    float* out = (float*)d_out;

    void *p;
    uint32_t *qh, *ql, *ph, *pl, *f1h, *f1l, *f2h, *f2l;
    uint32_t *xh, *xl, *o2h, *o2l, *x1h, *x1l, *fbh, *fbl;
    float *wpe, *qkv, *attno, *tmp, *x1, *spart, *pstat;
    cudaGetSymbolAddress(&p, g_wqkv_h);  qh  = (uint32_t*)p;
    cudaGetSymbolAddress(&p, g_wqkv_l);  ql  = (uint32_t*)p;
    cudaGetSymbolAddress(&p, g_wproj_h); ph  = (uint32_t*)p;
    cudaGetSymbolAddress(&p, g_wproj_l); pl  = (uint32_t*)p;
    cudaGetSymbolAddress(&p, g_wf1_h);   f1h = (uint32_t*)p;
    cudaGetSymbolAddress(&p, g_wf1_l);   f1l = (uint32_t*)p;
    cudaGetSymbolAddress(&p, g_wf2_h);   f2h = (uint32_t*)p;
    cudaGetSymbolAddress(&p, g_wf2_l);   f2l = (uint32_t*)p;
    cudaGetSymbolAddress(&p, g_xh);      xh  = (uint32_t*)p;
    cudaGetSymbolAddress(&p, g_xl);      xl  = (uint32_t*)p;
    cudaGetSymbolAddress(&p, g_o2h);     o2h = (uint32_t*)p;
    cudaGetSymbolAddress(&p, g_o2l);     o2l = (uint32_t*)p;
    cudaGetSymbolAddress(&p, g_x1h);     x1h = (uint32_t*)p;
    cudaGetSymbolAddress(&p, g_x1l);     x1l = (uint32_t*)p;
    cudaGetSymbolAddress(&p, g_fbh);     fbh = (uint32_t*)p;
    cudaGetSymbolAddress(&p, g_fbl);     fbl = (uint32_t*)p;
    cudaGetSymbolAddress(&p, g_wpe);     wpe = (float*)p;
    cudaGetSymbolAddress(&p, g_qkv);     qkv = (float*)p;
    cudaGetSymbolAddress(&p, g_attno);   attno = (float*)p;
    cudaGetSymbolAddress(&p, g_tmp);     tmp = (float*)p;
    cudaGetSymbolAddress(&p, g_x1);      x1  = (float*)p;
    cudaGetSymbolAddress(&p, g_spart);   spart = (float*)p;
    cudaGetSymbolAddress(&p, g_pstat);   pstat = (float*)p;

    // per-stage stat buffers: stage i -> psum = pstat + i*4096, psqr = psum + 2048
    float* ps0 = pstat;           float* pq0 = pstat + 2048;
    float* ps1 = pstat + 4096;    float* pq1 = pstat + 6144;
    float* ps2 = pstat + 8192;    float* pq2 = pstat + 10240;

    cudaFuncSetAttribute(mma_gemm2<false>, cudaFuncAttributeMaxDynamicSharedMemorySize, GEMM_SMEM_BYTES);
    cudaFuncSetAttribute(mma_gemm2<true>,  cudaFuncAttributeMaxDynamicSharedMemorySize, GEMM_SMEM_BYTES);
    static const int PE_SMEM = (19008 + 2304) * 4;
    cudaFuncSetAttribute(peconv_kernel, cudaFuncAttributeMaxDynamicSharedMemorySize, PE_SMEM);

    // 0. zero stat accumulators (graph-capturable memset)
    cudaMemsetAsync(pstat, 0, 3 * 2 * 2048 * sizeof(float));

    // 1. weight expansions -> packed bf16 hi/lo planes
    expand_w_pk<<<(512 * 3072 + 255) / 256, 256>>>(w_qkv,  qh,  ql,  768, 256);
    expand_w_pk<<<(512 * 1024 + 255) / 256, 256>>>(w_proj, ph,  pl,  256, 256);
    expand_w_pk<<<(512 * 2048 + 255) / 256, 256>>>(w_f1,   f1h, f1l, 512, 256);
    expand_w_pk<<<(1024 * 1024 + 255) / 256, 256>>>(w_f2,  f2h, f2l, 256, 512);
    expand_pe_kernel<<<(1024 * 16 * 9 + 255) / 256, 256>>>(w_pe, wpe);

    // 2. split x -> planes, qkv GEMM (no stats)
    split_pack<<<(int)((size_t)BATCH * 512 * (NSP / 4) / 256), 256>>>(x, xh, xl, BATCH * 512);
    mma_gemm2<false><<<dim3(32, 24, BATCH), 256, GEMM_SMEM_BYTES>>>(
        qh, ql, xh, xl, qkv, nullptr, nullptr, 3072, 1024);

    // 3. channel attention
    attn_qk<<<dim3(128, 4), 256>>>(qkv, spart);
    attn_av<<<dim3(128, 4), 256>>>(qkv, spart, attno);

    // 4. positional conv + residual -> o2 planes directly
    peconv_kernel<<<dim3(4, 64, BATCH), 256, PE_SMEM>>>(attno, wpe, o2h, o2l);

    // 5. proj GEMM (+stats) + BN residual -> x1 (+ planes)
    mma_gemm2<true><<<dim3(32, 8, BATCH), 256, GEMM_SMEM_BYTES>>>(
        ph, pl, o2h, o2l, tmp, ps0, pq0, 1024, 1024);
    ew_res_split<<<(int)((size_t)BATCH * 512 * (NSP / 4) / 256), 256>>>(
        x, tmp, ps0, pq0, gn, bn, x1, x1h, x1l, 1024);

    // 6. f1 GEMM (+stats) + BN relu -> fb planes
    mma_gemm2<true><<<dim3(32, 16, BATCH), 256, GEMM_SMEM_BYTES>>>(
        f1h, f1l, x1h, x1l, tmp, ps1, pq1, 2048, 1024);
    ew_relu_split<<<(int)((size_t)BATCH * 1024 * (NSP / 4) / 256), 256>>>(
        tmp, ps1, pq1, gf1, bf1, fbh, fbl, 2048);

    // 7. f2 GEMM (+stats) + BN residual -> out
    mma_gemm2<true><<<dim3(32, 8, BATCH), 256, GEMM_SMEM_BYTES>>>(
        f2h, f2l, fbh, fbl, tmp, ps2, pq2, 1024, 2048);
    ew_bn_res_kernel<<<(int)((size_t)4 * 1024 * NSP / 4 / 256), 256>>>(
        x1, tmp, ps2, pq2, gf2, bf2, out, 1024);

    (void)in_sizes; (void)n_in; (void)out_size;
}